// round 14
// baseline (speedup 1.0000x reference)
#include <cuda_runtime.h>
#include <cuda_bf16.h>
#include <cstdint>

#define B_  2
#define S_  2048
#define D_  1024
#define H_  16
#define HD_ 64
#define M_  (B_ * S_)          // 4096 rows

#define WIN_TILES 5            // 320-key decay window: 0.95^320 ~ 7e-8
#define LOG2DECAY -0.07400058144377693f

// ---------------- scratch (device globals: no allocation allowed) ----------
__device__ float  g_proj[M_ * D_];
__device__ float2 g_part[32 * 16];
__device__ float2 g_stats[32];

// GEMM operands stored PRE-TILED + PRE-SWIZZLED (smem image blocks):
//   A-type  (x, a): block (mtile*16 + chunk) of 16384 B = 128 rows x 128 B
//   W-type  (W^T) : block (ntile*16 + chunk) of 32768 B = 256 rows x 128 B
__device__ __align__(128) __nv_bfloat16 g_xhi[M_ * D_];
__device__ __align__(128) __nv_bfloat16 g_xlo[M_ * D_];
__device__ __align__(128) __nv_bfloat16 g_qhi[M_ * D_];
__device__ __align__(128) __nv_bfloat16 g_qlo[M_ * D_];
__device__ __align__(128) __nv_bfloat16 g_khi[M_ * D_];
__device__ __align__(128) __nv_bfloat16 g_klo[M_ * D_];
__device__ __align__(128) __nv_bfloat16 g_vthi[B_ * H_ * HD_ * S_];  // [b*1024+n][t]
__device__ __align__(128) __nv_bfloat16 g_vtlo[B_ * H_ * HD_ * S_];
__device__ __align__(128) __nv_bfloat16 g_ahi[M_ * D_];              // tiled
__device__ __align__(128) __nv_bfloat16 g_alo[M_ * D_];              // tiled
__device__ __align__(128) __nv_bfloat16 g_wthi[4][D_ * D_];          // tiled
__device__ __align__(128) __nv_bfloat16 g_wtlo[4][D_ * D_];          // tiled

extern __shared__ unsigned char sm_raw[];

#define SWZ(o) ((o) ^ (((o) >> 3) & 0x70))

// byte offset of element (m,k) in A-type tiled array
__device__ __forceinline__ size_t offA(int m, int k) {
    const int kc = k & 63;
    const unsigned w = SWZ((unsigned)((m & 127) * 128 + ((kc >> 3) << 4)));
    return (((size_t)((m >> 7) * 16 + (k >> 6))) << 14) + w + ((kc & 7) << 1);
}
// byte offset of element (n,k) in W-type tiled array
__device__ __forceinline__ size_t offW(int n, int k) {
    const int kc = k & 63;
    const unsigned w = SWZ((unsigned)((n & 255) * 128 + ((kc >> 3) << 4)));
    return (((size_t)((n >> 8) * 16 + (k >> 6))) << 15) + w + ((kc & 7) << 1);
}

// ---------------- PTX helpers ----------------------------------------------
__device__ __forceinline__ unsigned smem_u32(const void* p) {
    unsigned r;
    asm("{ .reg .u64 t; cvta.to.shared.u64 t, %1; cvt.u32.u64 %0, t; }"
        : "=r"(r) : "l"(p));
    return r;
}

#define MBARRIER_INIT(addr, cnt) \
    asm volatile("mbarrier.init.shared.b64 [%0], %1;" :: "r"(addr), "r"(cnt) : "memory")

#define MBARRIER_WAIT_PARITY(addr, ph) do {                                     \
    unsigned _m = (addr), _p = (ph), _d;                                        \
    asm volatile("{\n\t.reg .pred p;\n\t"                                       \
        "mbarrier.try_wait.parity.acquire.cta.shared::cta.b64 p, [%1], %2;\n\t" \
        "selp.b32 %0, 1, 0, p;\n\t}"                                            \
        : "=r"(_d) : "r"(_m), "r"(_p) : "memory");                              \
    if (!_d) {                                                                  \
        asm volatile("{\n\t.reg .pred P1;\n\t"                                  \
            "WL_%=:\n\t"                                                        \
            "mbarrier.try_wait.parity.acquire.cta.shared::cta.b64 P1, [%0], %1, 0x989680;\n\t" \
            "@P1 bra.uni WD_%=;\n\t"                                            \
            "bra.uni WL_%=;\n\t"                                                \
            "WD_%=:\n\t}"                                                       \
            :: "r"(_m), "r"(_p) : "memory");                                    \
    }                                                                           \
} while (0)

#define MBARRIER_EXPECT_TX(addr, tx) \
    asm volatile("mbarrier.arrive.expect_tx.shared.b64 _, [%0], %1;" \
                 :: "r"(addr), "r"(tx) : "memory")

#define CP_ASYNC16(dst, src) \
    asm volatile("cp.async.cg.shared.global [%0], [%1], 16;" :: "r"(dst), "l"(src))
#define CP_COMMIT() asm volatile("cp.async.commit_group;" ::: "memory")
#define CP_WAIT0()  asm volatile("cp.async.wait_group 0;" ::: "memory")
#define CP_BULK(dst, src, bytes, mbar) \
    asm volatile("cp.async.bulk.shared::cluster.global.mbarrier::complete_tx::bytes " \
                 "[%0], [%1], %2, [%3];" \
                 :: "r"(dst), "l"(src), "r"(bytes), "r"(mbar) : "memory")
#define FENCE_PROXY_ASYNC() asm volatile("fence.proxy.async.shared::cta;" ::: "memory")

__device__ __forceinline__ void split_store2(
    __nv_bfloat16* hi, __nv_bfloat16* lo, size_t idx, float v0, float v1)
{
    __nv_bfloat16 h0 = __float2bfloat16_rn(v0);
    __nv_bfloat16 h1 = __float2bfloat16_rn(v1);
    __nv_bfloat16 l0 = __float2bfloat16_rn(v0 - __bfloat162float(h0));
    __nv_bfloat16 l1 = __float2bfloat16_rn(v1 - __bfloat162float(h1));
    *(__nv_bfloat162*)(hi + idx) = __halves2bfloat162(h0, h1);
    *(__nv_bfloat162*)(lo + idx) = __halves2bfloat162(l0, l1);
}

#if defined(__CUDA_ARCH_FEAT_SM103_ALL)

#define TCGEN05_ALLOC(saddr, n) \
    asm volatile("tcgen05.alloc.cta_group::1.sync.aligned.shared::cta.b32 [%0], %1;" \
                 :: "r"(saddr), "r"(n) : "memory")
#define TCGEN05_DEALLOC(t, n) \
    asm volatile("tcgen05.dealloc.cta_group::1.sync.aligned.b32 %0, %1;" :: "r"(t), "r"(n))
#define TCGEN05_RELINQ() \
    asm volatile("tcgen05.relinquish_alloc_permit.cta_group::1.sync.aligned;")
#define TCGEN05_COMMIT(bar) \
    asm volatile("tcgen05.commit.cta_group::1.mbarrier::arrive::one.shared::cluster.b64 [%0];" \
                 :: "r"(bar) : "memory")
#define TCGEN05_FENCE_AFTER() \
    asm volatile("tcgen05.fence::after_thread_sync;" ::: "memory")
#define TCGEN05_FENCE_BEFORE() \
    asm volatile("tcgen05.fence::before_thread_sync;" ::: "memory")
#define TCGEN05_WAIT_LD() \
    asm volatile("tcgen05.wait::ld.sync.aligned;" ::: "memory")
#define TCGEN05_WAIT_ST() \
    asm volatile("tcgen05.wait::st.sync.aligned;" ::: "memory")

#define TCGEN05_LD_32X32B_X32(r, tmem_addr) \
    asm volatile( \
        "tcgen05.ld.sync.aligned.32x32b.x32.b32 " \
        "{%0, %1, %2, %3, %4, %5, %6, %7, " \
        " %8, %9, %10, %11, %12, %13, %14, %15, " \
        " %16, %17, %18, %19, %20, %21, %22, %23, " \
        " %24, %25, %26, %27, %28, %29, %30, %31}, [%32];" \
        : "=r"((r)[0]),  "=r"((r)[1]),  "=r"((r)[2]),  "=r"((r)[3]), \
          "=r"((r)[4]),  "=r"((r)[5]),  "=r"((r)[6]),  "=r"((r)[7]), \
          "=r"((r)[8]),  "=r"((r)[9]),  "=r"((r)[10]), "=r"((r)[11]), \
          "=r"((r)[12]), "=r"((r)[13]), "=r"((r)[14]), "=r"((r)[15]), \
          "=r"((r)[16]), "=r"((r)[17]), "=r"((r)[18]), "=r"((r)[19]), \
          "=r"((r)[20]), "=r"((r)[21]), "=r"((r)[22]), "=r"((r)[23]), \
          "=r"((r)[24]), "=r"((r)[25]), "=r"((r)[26]), "=r"((r)[27]), \
          "=r"((r)[28]), "=r"((r)[29]), "=r"((r)[30]), "=r"((r)[31]) \
        : "r"(tmem_addr))

#define TCGEN05_ST_32X32B_X8(tmem_addr, r) \
    asm volatile( \
        "tcgen05.st.sync.aligned.32x32b.x8.b32 [%0], " \
        "{%1, %2, %3, %4, %5, %6, %7, %8};" \
        :: "r"(tmem_addr), \
           "r"((r)[0]), "r"((r)[1]), "r"((r)[2]), "r"((r)[3]), \
           "r"((r)[4]), "r"((r)[5]), "r"((r)[6]), "r"((r)[7]) \
        : "memory")

__device__ __forceinline__ void mma_f16_ss(
    unsigned d_tmem, unsigned long long a_desc, unsigned long long b_desc,
    unsigned idesc, unsigned enable)
{
    asm volatile(
        "{\n\t.reg .pred p;\n\t"
        "setp.ne.u32 p, %4, 0;\n\t"
        "tcgen05.mma.cta_group::1.kind::f16 [%0], %1, %2, %3, {%5, %5, %5, %5}, p;\n\t"
        "}"
        :: "r"(d_tmem), "l"(a_desc), "l"(b_desc), "r"(idesc), "r"(enable), "r"(0u)
        : "memory");
}

__device__ __forceinline__ void mma_f16_ts(
    unsigned d_tmem, unsigned a_tmem, unsigned long long b_desc,
    unsigned idesc, unsigned enable)
{
    asm volatile(
        "{\n\t.reg .pred p;\n\t"
        "setp.ne.u32 p, %4, 0;\n\t"
        "tcgen05.mma.cta_group::1.kind::f16 [%0], [%1], %2, %3, {%5, %5, %5, %5}, p;\n\t"
        "}"
        :: "r"(d_tmem), "r"(a_tmem), "l"(b_desc), "r"(idesc), "r"(enable), "r"(0u)
        : "memory");
}

__device__ __forceinline__ unsigned long long sdesc(unsigned addr) {
    // SW128, Blackwell version=1, LBO=1, SBO=64
    return 0x4000404000010000ull | ((unsigned long long)(addr >> 4) & 0x3FFF);
}

#endif  // __CUDA_ARCH_FEAT_SM103_ALL

// ---------------- tcgen05 split-bf16 GEMM: C[4096x1024] = A*W^T + bias -----
// 192 threads: warp 5 = bulk-copy producer, warp 4 = MMA, warps 0-3 epilogue.
// smask selects pipeline depth: 0 => 1 stage (smem ~100 KB, 2 CTAs/SM for the
// 384-CTA qkv launch), 1 => 2 stages (proj, latency-pipelined).
#define GEMM_IDESC 0x08400490u   // F32 acc, bf16 a/b, N=256, M=128
#define STAGE_BYTES 98304
#define DYN_SMEM1 (2048 + 1 * STAGE_BYTES)
#define DYN_SMEM2 (2048 + 2 * STAGE_BYTES)
#define GT 192
// smem: [0]empty0 [8]empty1 [16]done [24]full0 [32]full1 [64]tmem [128]sred [1024]bias

__global__ __launch_bounds__(GT) void gemm_tc(
    int mode, int smask,
    const float* __restrict__ bq, const float* __restrict__ bk,
    const float* __restrict__ bv, const float* __restrict__ bo)
{
    const int tid = threadIdx.x;
    const int n0 = blockIdx.x << 8;     // 0..768
    const int m0 = blockIdx.y << 7;     // 0..3968
    const int z = blockIdx.z;

    const __nv_bfloat16 *Ahi, *Alo, *Bhi, *Blo;
    const float* bias;
    float* C = nullptr;
    __nv_bfloat16 *Chi = nullptr, *Clo = nullptr;
    int outKind;   // 0 = fp32 C + GN partials, 1 = split hi/lo, 2 = V^T split
    if (mode == 0) {
        Ahi = g_xhi; Alo = g_xlo;
        Bhi = g_wthi[z]; Blo = g_wtlo[z];
        bias = (z == 0) ? bq : (z == 1) ? bk : bv;
        if (z == 0)      { Chi = g_qhi; Clo = g_qlo; outKind = 1; }
        else if (z == 1) { Chi = g_khi; Clo = g_klo; outKind = 1; }
        else             { Chi = g_vthi; Clo = g_vtlo; outKind = 2; }
    } else {
        Ahi = g_ahi; Alo = g_alo;
        Bhi = g_wthi[3]; Blo = g_wtlo[3];
        bias = bo; C = g_proj; outKind = 0;
    }
    const int bb = m0 >> 11;                     // batch
    const int mchunk = (m0 & (S_ - 1)) >> 7;     // 0..15
    const int mt = m0 >> 7, nt = n0 >> 8;

#if defined(__CUDA_ARCH_FEAT_SM103_ALL)
    const unsigned sb = smem_u32(sm_raw);
    const int warp = tid >> 5, lane = tid & 31;

    if (tid == 0) {
        MBARRIER_INIT(sb + 0, 1);      // empty0
        MBARRIER_INIT(sb + 8, 1);      // empty1
        MBARRIER_INIT(sb + 16, 1);     // done
        MBARRIER_INIT(sb + 24, 1);     // full0 (expect_tx)
        MBARRIER_INIT(sb + 32, 1);     // full1 (expect_tx)
    }
    if (tid >= 32 && tid < 48) ((float*)(sm_raw + 128))[tid - 32] = 0.f;  // sred
    if (warp == 4) {
        TCGEN05_ALLOC(sb + 64, 256);
        TCGEN05_RELINQ();
    }
    if (tid < 128) {
        float* sbias = (float*)(sm_raw + 1024);
        sbias[tid] = bias[n0 + tid];
        sbias[tid + 128] = bias[n0 + 128 + tid];
    }
    __syncthreads();

    unsigned tmem;
    asm volatile("ld.shared.b32 %0, [%1];" : "=r"(tmem) : "r"(sb + 64));

    if (warp == 5) {
        // ---- producer: 4 bulk copies per chunk, issue-cost ~0 ----
        for (int c = 0; c < 16; c++) {
            const int s = c & smask, u = c >> smask;
            MBARRIER_WAIT_PARITY(sb + s * 8, (unsigned)((u & 1) ^ 1));
            if (lane == 0) {
                const unsigned fb = sb + 24 + s * 8;
                MBARRIER_EXPECT_TX(fb, (unsigned)STAGE_BYTES);
                const unsigned st = sb + 2048 + s * STAGE_BYTES;
                CP_BULK(st,         (const char*)Ahi + ((size_t)(mt * 16 + c) << 14), 16384u, fb);
                CP_BULK(st + 16384, (const char*)Alo + ((size_t)(mt * 16 + c) << 14), 16384u, fb);
                CP_BULK(st + 32768, (const char*)Bhi + ((size_t)(nt * 16 + c) << 15), 32768u, fb);
                CP_BULK(st + 65536, (const char*)Blo + ((size_t)(nt * 16 + c) << 15), 32768u, fb);
            }
        }
    } else if (warp == 4) {
        // ---- MMA warp ----
        for (int c = 0; c < 16; c++) {
            const int s = c & smask, u = c >> smask;
            MBARRIER_WAIT_PARITY(sb + 24 + s * 8, (unsigned)(u & 1));
            if (lane == 0) {
                const unsigned st = sb + 2048 + s * STAGE_BYTES;
                const unsigned long long dahi = sdesc(st);
                const unsigned long long dalo = sdesc(st + 16384);
                const unsigned long long dbhi = sdesc(st + 32768);
                const unsigned long long dblo = sdesc(st + 65536);
#pragma unroll
                for (int k = 0; k < 4; k++) {
                    const unsigned long long off = 2ull * k;
                    mma_f16_ss(tmem, dahi + off, dbhi + off, GEMM_IDESC,
                               (c == 0 && k == 0) ? 0u : 1u);
                    mma_f16_ss(tmem, dahi + off, dblo + off, GEMM_IDESC, 1u);
                    mma_f16_ss(tmem, dalo + off, dbhi + off, GEMM_IDESC, 1u);
                }
                TCGEN05_COMMIT(sb + s * 8);
            }
        }
        if (lane == 0) TCGEN05_COMMIT(sb + 16);
    }

    // ---- epilogue: all 192 threads, staged through smem for coalescing ----
    MBARRIER_WAIT_PARITY(sb + 16, 0);
    TCGEN05_FENCE_AFTER();
    const float* sbias = (const float*)(sm_raw + 1024);
    float* stage = (float*)(sm_raw + 2048);      // 128 x 33 fp32 (~16.9 KB)
    float* sred = (float*)(sm_raw + 128);        // 16 floats (GN partials)

    for (int cb = 0; cb < 8; cb++) {
        unsigned r[32];
        if (warp < 4) {
            TCGEN05_LD_32X32B_X32(r, tmem + cb * 32);
            TCGEN05_WAIT_LD();
            float* srow = stage + (warp * 32 + lane) * 33;
#pragma unroll
            for (int j = 0; j < 32; j++)
                srow[j] = __uint_as_float(r[j]) + sbias[cb * 32 + j];
        }
        __syncthreads();
        if (outKind == 0) {
            float ls = 0.f, lq = 0.f;
            for (int g = tid; g < 1024; g += GT) {
                const int row = g >> 3, cg = (g & 7) << 2;
                const float* s = stage + row * 33 + cg;
                float4 o = { s[0], s[1], s[2], s[3] };
                *(float4*)(C + (size_t)(m0 + row) * D_ + n0 + cb * 32 + cg) = o;
                ls += o.x + o.y + o.z + o.w;
                lq += o.x * o.x + o.y * o.y + o.z * o.z + o.w * o.w;
            }
#pragma unroll
            for (int off = 16; off; off >>= 1) {
                ls += __shfl_down_sync(0xffffffffu, ls, off);
                lq += __shfl_down_sync(0xffffffffu, lq, off);
            }
            if (lane == 0) {
                atomicAdd(sred + cb * 2, ls);
                atomicAdd(sred + cb * 2 + 1, lq);
            }
        } else if (outKind == 1) {
            for (int g = tid; g < 2048; g += GT) {
                const int row = g >> 4, cp = (g & 15) << 1;
                split_store2(Chi, Clo, (size_t)(m0 + row) * D_ + n0 + cb * 32 + cp,
                             stage[row * 33 + cp], stage[row * 33 + cp + 1]);
            }
        } else {
            for (int g = tid; g < 4096; g += GT) {
                const int col = g >> 7, row = g & 127;
                const float v = stage[row * 33 + col];
                __nv_bfloat16 hh = __float2bfloat16_rn(v);
                __nv_bfloat16 ll = __float2bfloat16_rn(v - __bfloat162float(hh));
                const size_t o = (size_t)(bb * 1024 + n0 + cb * 32 + col) * S_ + (m0 & (S_ - 1)) + row;
                Chi[o] = hh; Clo[o] = ll;
            }
        }
        __syncthreads();
    }
    if (outKind == 0 && tid < 4) {
        const float s = sred[(2 * tid) * 2] + sred[(2 * tid + 1) * 2];
        const float q = sred[(2 * tid) * 2 + 1] + sred[(2 * tid + 1) * 2 + 1];
        const int hg = (n0 >> 6) + tid;
        g_part[(bb * 16 + hg) * 16 + mchunk] = make_float2(s, q);
    }
    TCGEN05_FENCE_BEFORE();
    __syncthreads();
    if (warp == 4) TCGEN05_DEALLOC(tmem, 256);
#else
    for (int idx = tid; idx < 128 * 256; idx += GT) {
        const int i = idx >> 8, j = idx & 255;
        float acc = 0.f;
        for (int k = 0; k < D_; k++) {
            const float a = __bfloat162float(*(const __nv_bfloat16*)((const char*)Ahi + offA(m0 + i, k)))
                          + __bfloat162float(*(const __nv_bfloat16*)((const char*)Alo + offA(m0 + i, k)));
            const float w = __bfloat162float(*(const __nv_bfloat16*)((const char*)Bhi + offW(n0 + j, k)))
                          + __bfloat162float(*(const __nv_bfloat16*)((const char*)Blo + offW(n0 + j, k)));
            acc = fmaf(a, w, acc);
        }
        const float v = acc + bias[n0 + j];
        const int m = m0 + i;
        if (outKind == 1) {
            const size_t o = (size_t)m * D_ + n0 + j;
            __nv_bfloat16 h = __float2bfloat16_rn(v);
            Chi[o] = h;
            Clo[o] = __float2bfloat16_rn(v - __bfloat162float(h));
        } else if (outKind == 2) {
            const size_t o = (size_t)((m >> 11) * 1024 + n0 + j) * S_ + (m & (S_ - 1));
            __nv_bfloat16 h = __float2bfloat16_rn(v);
            Chi[o] = h;
            Clo[o] = __float2bfloat16_rn(v - __bfloat162float(h));
        } else {
            C[(size_t)m * D_ + n0 + j] = v;
            float* gp = (float*)&g_part[(bb * 16 + ((n0 + j) >> 6)) * 16 + mchunk];
            atomicAdd(gp, v);
            atomicAdd(gp + 1, v * v);
        }
    }
#endif
}

// ---------------- merged prep: W^T tiled split (z<4) + x tiled split (z==4) -
__global__ __launch_bounds__(256) void prep(
    const float* __restrict__ x,
    const float* __restrict__ W0, const float* __restrict__ W1,
    const float* __restrict__ W2, const float* __restrict__ W3)
{
    const int z = blockIdx.z;
    const int tx = threadIdx.x, ty = threadIdx.y;
    const int tid = ty * 32 + tx;
    if (z == 4) {
        if (blockIdx.x == 0 && blockIdx.y == 0) {
            for (int i = tid; i < 512; i += 256) g_part[i] = make_float2(0.f, 0.f);
        }
        const int u0 = (blockIdx.y * 32 + blockIdx.x) * 256 + tid;
#pragma unroll
        for (int r = 0; r < 4; r++) {
            const int i = (u0 + r * 262144) << 2;
            float4 v = *(const float4*)(x + i);
            const size_t o = offA(i >> 10, i & 1023);
            __nv_bfloat16 h0 = __float2bfloat16_rn(v.x);
            __nv_bfloat16 h1 = __float2bfloat16_rn(v.y);
            __nv_bfloat16 h2 = __float2bfloat16_rn(v.z);
            __nv_bfloat16 h3 = __float2bfloat16_rn(v.w);
            *(__nv_bfloat162*)((char*)g_xhi + o)     = __halves2bfloat162(h0, h1);
            *(__nv_bfloat162*)((char*)g_xhi + o + 4) = __halves2bfloat162(h2, h3);
            __nv_bfloat16 l0 = __float2bfloat16_rn(v.x - __bfloat162float(h0));
            __nv_bfloat16 l1 = __float2bfloat16_rn(v.y - __bfloat162float(h1));
            __nv_bfloat16 l2 = __float2bfloat16_rn(v.z - __bfloat162float(h2));
            __nv_bfloat16 l3 = __float2bfloat16_rn(v.w - __bfloat162float(h3));
            *(__nv_bfloat162*)((char*)g_xlo + o)     = __halves2bfloat162(l0, l1);
            *(__nv_bfloat162*)((char*)g_xlo + o + 4) = __halves2bfloat162(l2, l3);
        }
        return;
    }
    const float* W = (z == 0) ? W0 : (z == 1) ? W1 : (z == 2) ? W2 : W3;
    __nv_bfloat16* Hi = g_wthi[z];
    __nv_bfloat16* Lo = g_wtlo[z];
    __shared__ float t[32][33];
    const int n0 = blockIdx.x << 5, k0 = blockIdx.y << 5;
#pragma unroll
    for (int i = 0; i < 4; i++)
        t[ty + 8 * i][tx] = W[(size_t)(k0 + ty + 8 * i) * D_ + n0 + tx];
    __syncthreads();
#pragma unroll
    for (int i = 0; i < 4; i++) {
        const float v = t[tx][ty + 8 * i];
        __nv_bfloat16 h = __float2bfloat16_rn(v);
        __nv_bfloat16 l = __float2bfloat16_rn(v - __bfloat162float(h));
        const size_t o = offW(n0 + ty + 8 * i, k0 + tx);
        *(__nv_bfloat16*)((char*)Hi + o) = h;
        *(__nv_bfloat16*)((char*)Lo + o) = l;
    }
}

// ---------------- tcgen05 windowed decay attention ---------------------------
// CTA: 128 q rows x one (b,h). 256 threads, single KV stage, in-place S,
// TMEM 128 cols, 3 CTAs/SM. Epilogue writes g_a in GEMM-tiled layout.
#define ATT_IDESC 0x08100490u   // F32 acc, bf16, N=64, M=128
#define SO_BAR_S 0
#define SO_BAR_V 8
#define SO_TMEM  16
#define SO_TBL   1024
#define SO_QHI   3072
#define SO_QLO   (SO_QHI + 16384)
#define SO_KHI   (SO_QLO + 16384)        // 35840
#define SO_KLO   (SO_KHI + 8192)
#define SO_VHI   (SO_KLO + 8192)
#define SO_VLO   (SO_VHI + 8192)
#define ATT_SMEM (SO_VLO + 8192)         // 68608 bytes -> 3 CTAs/SM
// TMEM cols: O [0,64), S [64,128). Convert in-place: hi -> 64+, lo -> 96+.

__global__ __launch_bounds__(256, 3) void attn_tc()
{
    const int tid = threadIdx.x;
    const int bh = blockIdx.x;            // 0..31
    const int qp = 15 - blockIdx.y;       // heavy tiles first
    const int b = bh >> 4, h = bh & 15;
    const int qb = qp << 7;               // token base within batch
    const int qt0 = qp << 1;
    int jt0 = qt0 - WIN_TILES; if (jt0 < 0) jt0 = 0;
    const int nt = (qt0 + 1) - jt0 + 1;

#if defined(__CUDA_ARCH_FEAT_SM103_ALL)
    const unsigned sb = smem_u32(sm_raw);
    const int warp = tid >> 5, lane = tid & 31;
    const int sub = warp & 3;             // TMEM subpartition
    const int chalf = warp >> 2;          // column half (0/1)

    if (warp == 0) { TCGEN05_ALLOC(sb + SO_TMEM, 128); TCGEN05_RELINQ(); }
    if (tid == 0) {
        MBARRIER_INIT(sb + SO_BAR_S, 1);
        MBARRIER_INIT(sb + SO_BAR_V, 1);
    }
    float* tbl = (float*)(sm_raw + SO_TBL);
    for (int d = tid; d < 512; d += 256)
        tbl[d] = exp2f((float)d * LOG2DECAY);

    const char* kh0 = (const char*)(g_khi + ((size_t)(b * S_)) * D_ + h * HD_);
    const char* kl0 = (const char*)(g_klo + ((size_t)(b * S_)) * D_ + h * HD_);
    const char* vh0 = (const char*)(g_vthi + (size_t)bh * HD_ * S_);
    const char* vl0 = (const char*)(g_vtlo + (size_t)bh * HD_ * S_);

    // Q tiles: 128 rows x 128B, hi+lo
    {
        const char* qh = (const char*)(g_qhi + ((size_t)(b * S_ + qb)) * D_ + h * HD_);
        const char* ql = (const char*)(g_qlo + ((size_t)(b * S_ + qb)) * D_ + h * HD_);
        for (int g = tid; g < 1024; g += 256) {
            const int row = g >> 3, c = g & 7;
            const unsigned so = SWZ((unsigned)(row * 128 + c * 16));
            CP_ASYNC16(sb + SO_QHI + so, qh + (size_t)row * (D_ * 2) + c * 16);
            CP_ASYNC16(sb + SO_QLO + so, ql + (size_t)row * (D_ * 2) + c * 16);
        }
    }
    CP_COMMIT();
    __syncthreads();

    unsigned tmem;
    asm volatile("ld.shared.b32 %0, [%1];" : "=r"(tmem) : "r"(sb + SO_TMEM));

    const unsigned long long dQhi = sdesc(sb + SO_QHI), dQlo = sdesc(sb + SO_QLO);
    const unsigned long long dKhi = sdesc(sb + SO_KHI), dKlo = sdesc(sb + SO_KLO);
    const unsigned long long dVhi = sdesc(sb + SO_VHI), dVlo = sdesc(sb + SO_VLO);

    unsigned phs = 0, phv = 0;
    const int qrow = qb + sub * 32 + lane;                 // q token within batch

    for (int it = 0; it < nt; it++) {
        const int jt = jt0 + it;

        // V-MMA(it-1) must finish before KV smem / S cols are reused
        if (it > 0) { MBARRIER_WAIT_PARITY(sb + SO_BAR_V, phv); phv ^= 1; }

        // load KV(it)
        {
            const size_t koff = (size_t)(jt << 6);
            for (int g = tid; g < 512; g += 256) {
                const int row = g >> 3, c = g & 7;
                const unsigned so = SWZ((unsigned)(row * 128 + c * 16));
                CP_ASYNC16(sb + SO_KHI + so, kh0 + (koff + row) * (D_ * 2) + c * 16);
                CP_ASYNC16(sb + SO_KLO + so, kl0 + (koff + row) * (D_ * 2) + c * 16);
                CP_ASYNC16(sb + SO_VHI + so, vh0 + ((size_t)row * S_ + (jt << 6)) * 2 + c * 16);
                CP_ASYNC16(sb + SO_VLO + so, vl0 + ((size_t)row * S_ + (jt << 6)) * 2 + c * 16);
            }
            CP_COMMIT();
        }
        CP_WAIT0();
        FENCE_PROXY_ASYNC();
        __syncthreads();

        // S = Q K^T  (S at tmem+64, fp32)
        if (tid == 0) {
#pragma unroll
            for (int k = 0; k < 4; k++) {
                const unsigned long long off = 2ull * k;
                mma_f16_ss(tmem + 64, dQhi + off, dKhi + off, ATT_IDESC, k > 0 ? 1u : 0u);
                mma_f16_ss(tmem + 64, dQhi + off, dKlo + off, ATT_IDESC, 1u);
                mma_f16_ss(tmem + 64, dQlo + off, dKhi + off, ATT_IDESC, 1u);
            }
            TCGEN05_COMMIT(sb + SO_BAR_S);
        }
        MBARRIER_WAIT_PARITY(sb + SO_BAR_S, phs); phs ^= 1;
        TCGEN05_FENCE_AFTER();

        // convert: read S fp32, mask, split -> write back IN PLACE as bf16x2
        const int kbase = jt << 6;
        {
            unsigned r[32];
            TCGEN05_LD_32X32B_X32(r, tmem + 64 + chalf * 32);
            TCGEN05_WAIT_LD();
            __syncthreads();             // ALL reads complete before any write
#pragma unroll
            for (int half = 0; half < 2; half++) {
                unsigned hi8[8], lo8[8];
#pragma unroll
                for (int c = 0; c < 16; c += 2) {
                    const int col = chalf * 32 + half * 16 + c;
                    const int d0 = qrow - (kbase + col);
                    const int d1 = d0 - 1;
                    const float f0 = (d0 >= 0) ? tbl[d0] : 0.f;
                    const float f1 = (d1 >= 0) ? tbl[d1] : 0.f;
                    const float v0 = __uint_as_float(r[half * 16 + c]) * f0;
                    const float v1 = __uint_as_float(r[half * 16 + c + 1]) * f1;
                    __nv_bfloat16 h0 = __float2bfloat16_rn(v0);
                    __nv_bfloat16 h1 = __float2bfloat16_rn(v1);
                    __nv_bfloat16 l0 = __float2bfloat16_rn(v0 - __bfloat162float(h0));
                    __nv_bfloat16 l1 = __float2bfloat16_rn(v1 - __bfloat162float(h1));
                    __nv_bfloat162 ph = __halves2bfloat162(h0, h1);
                    __nv_bfloat162 pl = __halves2bfloat162(l0, l1);
                    hi8[c >> 1] = *reinterpret_cast<unsigned*>(&ph);
                    lo8[c >> 1] = *reinterpret_cast<unsigned*>(&pl);
                }
                const unsigned cbase = (unsigned)(chalf * 16 + half * 8);
                TCGEN05_ST_32X32B_X8(tmem + 64 + cbase, hi8);
                TCGEN05_ST_32X32B_X8(tmem + 96 + cbase, lo8);
            }
            TCGEN05_WAIT_ST();
        }
        TCGEN05_FENCE_BEFORE();
        __syncthreads();

        // O += S V  (TS: A = S bf16 in TMEM, B = V^T in smem)
        if (tid == 0) {
            TCGEN05_FENCE_AFTER();
#pragma unroll
            for (int k = 0; k < 4; k++) {
                const unsigned long long off = 2ull * k;
                mma_f16_ts(tmem, tmem + 64 + k * 8, dVhi + off, ATT_IDESC,
                           (it == 0 && k == 0) ? 0u : 1u);
                mma_f16_ts(tmem, tmem + 64 + k * 8, dVlo + off, ATT_IDESC, 1u);
                mma_f16_ts(tmem, tmem + 96 + k * 8, dVhi + off, ATT_IDESC, 1u);
            }
            TCGEN05_COMMIT(sb + SO_BAR_V);
        }
    }
    MBARRIER_WAIT_PARITY(sb + SO_BAR_V, phv);
    TCGEN05_FENCE_AFTER();

    // epilogue: O -> smem (stride-65) -> g_a in GEMM-tiled swizzled layout
    {
        float* stg = (float*)(sm_raw + SO_QHI);   // 33 KB in dead Q/K region
        unsigned r[32];
        TCGEN05_LD_32X32B_X32(r, tmem + chalf * 32);
        TCGEN05_WAIT_LD();
        float* srow = stg + (sub * 32 + lane) * 65 + chalf * 32;
#pragma unroll
        for (int j = 0; j < 32; j++) srow[j] = __uint_as_float(r[j]);
        TCGEN05_FENCE_BEFORE();
        __syncthreads();
        const size_t abase = ((size_t)((((b * S_) + qb) >> 7) * 16 + h)) << 14;
        for (int g = tid; g < 4096; g += 256) {
            const int row = g >> 5, cp = (g & 31) << 1;
            const size_t o = abase + SWZ((unsigned)(row * 128 + ((cp >> 3) << 4))) + ((cp & 7) << 1);
            const float v0 = stg[row * 65 + cp], v1 = stg[row * 65 + cp + 1];
            __nv_bfloat16 h0 = __float2bfloat16_rn(v0);
            __nv_bfloat16 h1 = __float2bfloat16_rn(v1);
            __nv_bfloat16 l0 = __float2bfloat16_rn(v0 - __bfloat162float(h0));
            __nv_bfloat16 l1 = __float2bfloat16_rn(v1 - __bfloat162float(h1));
            *(__nv_bfloat162*)((char*)g_ahi + o) = __halves2bfloat162(h0, h1);
            *(__nv_bfloat162*)((char*)g_alo + o) = __halves2bfloat162(l0, l1);
        }
    }
    __syncthreads();
    if (warp == 0) TCGEN05_DEALLOC(tmem, 128);
#else
    // -------- correct (very slow) fallback: never runs on GB300 -------------
    const int jlo = jt0 << 6;
    for (int e = tid; e < 128 * HD_; e += 256) {
        const int i = e >> 6, d = e & 63;
        const int qr = qb + i;
        float acc = 0.f;
        for (int j = jlo; j <= qr; j++) {
            float s = 0.f;
            const size_t qo = (size_t)(b * S_ + qr) * D_ + h * HD_;
            const size_t ko = (size_t)(b * S_ + j) * D_ + h * HD_;
            for (int k = 0; k < HD_; k++) {
                const float qv = __bfloat162float(g_qhi[qo + k]) + __bfloat162float(g_qlo[qo + k]);
                const float kv = __bfloat162float(g_khi[ko + k]) + __bfloat162float(g_klo[ko + k]);
                s = fmaf(qv, kv, s);
            }
            const float f = exp2f((float)(qr - j) * LOG2DECAY);
            const size_t vo = (size_t)(bh * HD_ + d) * S_ + j;
            const float vv = __bfloat162float(g_vthi[vo]) + __bfloat162float(g_vtlo[vo]);
            acc = fmaf(s * f, vv, acc);
        }
        const size_t o = offA(b * S_ + qr, h * HD_ + d);
        __nv_bfloat16 hh = __float2bfloat16_rn(acc);
        *(__nv_bfloat16*)((char*)g_ahi + o) = hh;
        *(__nv_bfloat16*)((char*)g_alo + o) =
            __float2bfloat16_rn(acc - __bfloat162float(hh));
    }
#endif
}

// ---------------- GroupNorm (partials fused into proj epilogue) -------------
__global__ void gn_stats()
{
    const int g = threadIdx.x;
    float s = 0.f, q = 0.f;
    for (int c = 0; c < 16; c++) {
        float2 p = g_part[g * 16 + c];
        s += p.x; q += p.y;
    }
    const float n = (float)(S_ * HD_);
    const float mu = s / n;
    const float var = q / n - mu * mu;
    g_stats[g] = make_float2(mu, rsqrtf(var + 1e-5f));
}

__global__ __launch_bounds__(256) void gn_apply(
    const float* __restrict__ gamma, const float* __restrict__ beta,
    float* __restrict__ out)
{
    const int t = blockIdx.x * 256 + threadIdx.x;
    const int base = t << 2;
    const int d = base & (D_ - 1);
    const int row = base >> 10;
    const int b = row >> 11;
    const float2 st = g_stats[(b << 4) | (d >> 6)];
    const float4 v  = *(const float4*)(g_proj + base);
    const float4 gm = *(const float4*)(gamma + d);
    const float4 bt = *(const float4*)(beta + d);
    float4 o;
    o.x = (v.x - st.x) * st.y * gm.x + bt.x;
    o.y = (v.y - st.x) * st.y * gm.y + bt.y;
    o.z = (v.z - st.x) * st.y * gm.z + bt.z;
    o.w = (v.w - st.x) * st.y * gm.w + bt.w;
    *(float4*)(out + base) = o;
}

// ---------------- launch ----------------------------------------------------
extern "C" void kernel_launch(void* const* d_in, const int* in_sizes, int n_in,
                              void* d_out, int out_size)
{
    (void)in_sizes; (void)n_in; (void)out_size;
    const float* x     = (const float*)d_in[0];
    const float* Wq    = (const float*)d_in[1];
    const float* bq    = (const float*)d_in[2];
    const float* Wk    = (const float*)d_in[3];
    const float* bk    = (const float*)d_in[4];
    const float* Wv    = (const float*)d_in[5];
    const float* bv    = (const float*)d_in[6];
    const float* Wo    = (const float*)d_in[7];
    const float* bo    = (const float*)d_in[8];
    const float* gamma = (const float*)d_in[9];
    const float* beta  = (const float*)d_in[10];
    float* out = (float*)d_out;

    cudaFuncSetAttribute(gemm_tc,
                         cudaFuncAttributeMaxDynamicSharedMemorySize, DYN_SMEM2);
    cudaFuncSetAttribute(attn_tc,
                         cudaFuncAttributeMaxDynamicSharedMemorySize, ATT_SMEM);

    prep<<<dim3(32, 32, 5), dim3(32, 8)>>>(x, Wq, Wk, Wv, Wo);
    gemm_tc<<<dim3(4, 32, 3), GT, DYN_SMEM1>>>(0, 0, bq, bk, bv, bo);   // 1 stage, 2 CTAs/SM
    attn_tc<<<dim3(32, 16), 256, ATT_SMEM>>>();
    gemm_tc<<<dim3(4, 32, 1), GT, DYN_SMEM2>>>(1, 1, bq, bk, bv, bo);   // 2 stages
    gn_stats<<<1, 32>>>();
    gn_apply<<<(M_ * D_) / (256 * 4), 256>>>(gamma, beta, out);
}

// round 15
// speedup vs baseline: 1.0881x; 1.0881x over previous
#include <cuda_runtime.h>
#include <cuda_bf16.h>
#include <cstdint>

#define B_  2
#define S_  2048
#define D_  1024
#define H_  16
#define HD_ 64
#define M_  (B_ * S_)          // 4096 rows

#define WIN_TILES 5            // 320-key decay window: 0.95^320 ~ 7e-8
#define LOG2DECAY -0.07400058144377693f

// ---------------- scratch (device globals: no allocation allowed) ----------
__device__ float  g_proj[M_ * D_];
__device__ float2 g_part[32 * 16];
__device__ float2 g_stats[32];

// GEMM operands stored PRE-TILED + PRE-SWIZZLED (smem image blocks):
//   A-type  (x, a): block (mtile*16 + chunk) of 16384 B = 128 rows x 128 B
//   W-type  (W^T) : block (ntile*16 + chunk) of 32768 B = 256 rows x 128 B
__device__ __align__(128) __nv_bfloat16 g_xhi[M_ * D_];
__device__ __align__(128) __nv_bfloat16 g_xlo[M_ * D_];
__device__ __align__(128) __nv_bfloat16 g_qhi[M_ * D_];
__device__ __align__(128) __nv_bfloat16 g_qlo[M_ * D_];
__device__ __align__(128) __nv_bfloat16 g_khi[M_ * D_];
__device__ __align__(128) __nv_bfloat16 g_klo[M_ * D_];
__device__ __align__(128) __nv_bfloat16 g_vthi[B_ * H_ * HD_ * S_];  // [b*1024+n][t]
__device__ __align__(128) __nv_bfloat16 g_vtlo[B_ * H_ * HD_ * S_];
__device__ __align__(128) __nv_bfloat16 g_ahi[M_ * D_];              // tiled
__device__ __align__(128) __nv_bfloat16 g_alo[M_ * D_];              // tiled
__device__ __align__(128) __nv_bfloat16 g_wthi[4][D_ * D_];          // tiled
__device__ __align__(128) __nv_bfloat16 g_wtlo[4][D_ * D_];          // tiled

extern __shared__ unsigned char sm_raw[];

#define SWZ(o) ((o) ^ (((o) >> 3) & 0x70))

// byte offset of element (m,k) in A-type tiled array
__device__ __forceinline__ size_t offA(int m, int k) {
    const int kc = k & 63;
    const unsigned w = SWZ((unsigned)((m & 127) * 128 + ((kc >> 3) << 4)));
    return (((size_t)((m >> 7) * 16 + (k >> 6))) << 14) + w + ((kc & 7) << 1);
}
// byte offset of element (n,k) in W-type tiled array
__device__ __forceinline__ size_t offW(int n, int k) {
    const int kc = k & 63;
    const unsigned w = SWZ((unsigned)((n & 255) * 128 + ((kc >> 3) << 4)));
    return (((size_t)((n >> 8) * 16 + (k >> 6))) << 15) + w + ((kc & 7) << 1);
}

// ---------------- PTX helpers ----------------------------------------------
__device__ __forceinline__ unsigned smem_u32(const void* p) {
    unsigned r;
    asm("{ .reg .u64 t; cvta.to.shared.u64 t, %1; cvt.u32.u64 %0, t; }"
        : "=r"(r) : "l"(p));
    return r;
}

#define MBARRIER_INIT(addr, cnt) \
    asm volatile("mbarrier.init.shared.b64 [%0], %1;" :: "r"(addr), "r"(cnt) : "memory")

#define MBARRIER_WAIT_PARITY(addr, ph) do {                                     \
    unsigned _m = (addr), _p = (ph), _d;                                        \
    asm volatile("{\n\t.reg .pred p;\n\t"                                       \
        "mbarrier.try_wait.parity.acquire.cta.shared::cta.b64 p, [%1], %2;\n\t" \
        "selp.b32 %0, 1, 0, p;\n\t}"                                            \
        : "=r"(_d) : "r"(_m), "r"(_p) : "memory");                              \
    if (!_d) {                                                                  \
        asm volatile("{\n\t.reg .pred P1;\n\t"                                  \
            "WL_%=:\n\t"                                                        \
            "mbarrier.try_wait.parity.acquire.cta.shared::cta.b64 P1, [%0], %1, 0x989680;\n\t" \
            "@P1 bra.uni WD_%=;\n\t"                                            \
            "bra.uni WL_%=;\n\t"                                                \
            "WD_%=:\n\t}"                                                       \
            :: "r"(_m), "r"(_p) : "memory");                                    \
    }                                                                           \
} while (0)

#define MBARRIER_EXPECT_TX(addr, tx) \
    asm volatile("mbarrier.arrive.expect_tx.shared.b64 _, [%0], %1;" \
                 :: "r"(addr), "r"(tx) : "memory")

#define CP_ASYNC16(dst, src) \
    asm volatile("cp.async.cg.shared.global [%0], [%1], 16;" :: "r"(dst), "l"(src))
#define CP_COMMIT() asm volatile("cp.async.commit_group;" ::: "memory")
#define CP_WAIT0()  asm volatile("cp.async.wait_group 0;" ::: "memory")
#define CP_BULK(dst, src, bytes, mbar) \
    asm volatile("cp.async.bulk.shared::cluster.global.mbarrier::complete_tx::bytes " \
                 "[%0], [%1], %2, [%3];" \
                 :: "r"(dst), "l"(src), "r"(bytes), "r"(mbar) : "memory")
#define FENCE_PROXY_ASYNC() asm volatile("fence.proxy.async.shared::cta;" ::: "memory")

__device__ __forceinline__ void split_store2(
    __nv_bfloat16* hi, __nv_bfloat16* lo, size_t idx, float v0, float v1)
{
    __nv_bfloat16 h0 = __float2bfloat16_rn(v0);
    __nv_bfloat16 h1 = __float2bfloat16_rn(v1);
    __nv_bfloat16 l0 = __float2bfloat16_rn(v0 - __bfloat162float(h0));
    __nv_bfloat16 l1 = __float2bfloat16_rn(v1 - __bfloat162float(h1));
    *(__nv_bfloat162*)(hi + idx) = __halves2bfloat162(h0, h1);
    *(__nv_bfloat162*)(lo + idx) = __halves2bfloat162(l0, l1);
}

#if defined(__CUDA_ARCH_FEAT_SM103_ALL)

#define TCGEN05_ALLOC(saddr, n) \
    asm volatile("tcgen05.alloc.cta_group::1.sync.aligned.shared::cta.b32 [%0], %1;" \
                 :: "r"(saddr), "r"(n) : "memory")
#define TCGEN05_DEALLOC(t, n) \
    asm volatile("tcgen05.dealloc.cta_group::1.sync.aligned.b32 %0, %1;" :: "r"(t), "r"(n))
#define TCGEN05_RELINQ() \
    asm volatile("tcgen05.relinquish_alloc_permit.cta_group::1.sync.aligned;")
#define TCGEN05_COMMIT(bar) \
    asm volatile("tcgen05.commit.cta_group::1.mbarrier::arrive::one.shared::cluster.b64 [%0];" \
                 :: "r"(bar) : "memory")
#define TCGEN05_FENCE_AFTER() \
    asm volatile("tcgen05.fence::after_thread_sync;" ::: "memory")
#define TCGEN05_FENCE_BEFORE() \
    asm volatile("tcgen05.fence::before_thread_sync;" ::: "memory")
#define TCGEN05_WAIT_LD() \
    asm volatile("tcgen05.wait::ld.sync.aligned;" ::: "memory")
#define TCGEN05_WAIT_ST() \
    asm volatile("tcgen05.wait::st.sync.aligned;" ::: "memory")

#define TCGEN05_LD_32X32B_X32(r, tmem_addr) \
    asm volatile( \
        "tcgen05.ld.sync.aligned.32x32b.x32.b32 " \
        "{%0, %1, %2, %3, %4, %5, %6, %7, " \
        " %8, %9, %10, %11, %12, %13, %14, %15, " \
        " %16, %17, %18, %19, %20, %21, %22, %23, " \
        " %24, %25, %26, %27, %28, %29, %30, %31}, [%32];" \
        : "=r"((r)[0]),  "=r"((r)[1]),  "=r"((r)[2]),  "=r"((r)[3]), \
          "=r"((r)[4]),  "=r"((r)[5]),  "=r"((r)[6]),  "=r"((r)[7]), \
          "=r"((r)[8]),  "=r"((r)[9]),  "=r"((r)[10]), "=r"((r)[11]), \
          "=r"((r)[12]), "=r"((r)[13]), "=r"((r)[14]), "=r"((r)[15]), \
          "=r"((r)[16]), "=r"((r)[17]), "=r"((r)[18]), "=r"((r)[19]), \
          "=r"((r)[20]), "=r"((r)[21]), "=r"((r)[22]), "=r"((r)[23]), \
          "=r"((r)[24]), "=r"((r)[25]), "=r"((r)[26]), "=r"((r)[27]), \
          "=r"((r)[28]), "=r"((r)[29]), "=r"((r)[30]), "=r"((r)[31]) \
        : "r"(tmem_addr))

#define TCGEN05_ST_32X32B_X8(tmem_addr, r) \
    asm volatile( \
        "tcgen05.st.sync.aligned.32x32b.x8.b32 [%0], " \
        "{%1, %2, %3, %4, %5, %6, %7, %8};" \
        :: "r"(tmem_addr), \
           "r"((r)[0]), "r"((r)[1]), "r"((r)[2]), "r"((r)[3]), \
           "r"((r)[4]), "r"((r)[5]), "r"((r)[6]), "r"((r)[7]) \
        : "memory")

__device__ __forceinline__ void mma_f16_ss(
    unsigned d_tmem, unsigned long long a_desc, unsigned long long b_desc,
    unsigned idesc, unsigned enable)
{
    asm volatile(
        "{\n\t.reg .pred p;\n\t"
        "setp.ne.u32 p, %4, 0;\n\t"
        "tcgen05.mma.cta_group::1.kind::f16 [%0], %1, %2, %3, {%5, %5, %5, %5}, p;\n\t"
        "}"
        :: "r"(d_tmem), "l"(a_desc), "l"(b_desc), "r"(idesc), "r"(enable), "r"(0u)
        : "memory");
}

__device__ __forceinline__ void mma_f16_ts(
    unsigned d_tmem, unsigned a_tmem, unsigned long long b_desc,
    unsigned idesc, unsigned enable)
{
    asm volatile(
        "{\n\t.reg .pred p;\n\t"
        "setp.ne.u32 p, %4, 0;\n\t"
        "tcgen05.mma.cta_group::1.kind::f16 [%0], [%1], %2, %3, {%5, %5, %5, %5}, p;\n\t"
        "}"
        :: "r"(d_tmem), "r"(a_tmem), "l"(b_desc), "r"(idesc), "r"(enable), "r"(0u)
        : "memory");
}

__device__ __forceinline__ unsigned long long sdesc(unsigned addr) {
    // SW128, Blackwell version=1, LBO=1, SBO=64
    return 0x4000404000010000ull | ((unsigned long long)(addr >> 4) & 0x3FFF);
}

#endif  // __CUDA_ARCH_FEAT_SM103_ALL

// ---------------- tcgen05 split-bf16 GEMM: C = A*W^T + bias -----------------
// Tile 128(M) x 128(N), K chunk 64, SINGLE 64 KB stage -> 3 CTAs/SM.
// 192 threads: warp 5 = bulk producer, warp 4 = MMA, warps 0-3 = epilogue.
#define GEMM_IDESC 0x08200490u   // F32 acc, bf16 a/b, N=128, M=128
#define STAGE_BYTES 65536
#define DYN_SMEM (2048 + STAGE_BYTES)
#define GT 192
// smem: [0]empty [16]done [24]full [64]tmem [128]sred [1024]bias [2048+]stage

__global__ __launch_bounds__(GT, 3) void gemm_tc(
    int mode,
    const float* __restrict__ bq, const float* __restrict__ bk,
    const float* __restrict__ bv, const float* __restrict__ bo)
{
    const int tid = threadIdx.x;
    const int n0 = blockIdx.x << 7;     // 0..896, step 128
    const int m0 = blockIdx.y << 7;     // 0..3968
    const int z = blockIdx.z;

    const __nv_bfloat16 *Ahi, *Alo, *Bhi, *Blo;
    const float* bias;
    float* C = nullptr;
    __nv_bfloat16 *Chi = nullptr, *Clo = nullptr;
    int outKind;   // 0 = fp32 C + GN partials, 1 = split hi/lo, 2 = V^T split
    if (mode == 0) {
        Ahi = g_xhi; Alo = g_xlo;
        Bhi = g_wthi[z]; Blo = g_wtlo[z];
        bias = (z == 0) ? bq : (z == 1) ? bk : bv;
        if (z == 0)      { Chi = g_qhi; Clo = g_qlo; outKind = 1; }
        else if (z == 1) { Chi = g_khi; Clo = g_klo; outKind = 1; }
        else             { Chi = g_vthi; Clo = g_vtlo; outKind = 2; }
    } else {
        Ahi = g_ahi; Alo = g_alo;
        Bhi = g_wthi[3]; Blo = g_wtlo[3];
        bias = bo; C = g_proj; outKind = 0;
    }
    const int bb = m0 >> 11;                     // batch
    const int mchunk = (m0 & (S_ - 1)) >> 7;     // 0..15
    const int mt = m0 >> 7;
    const int nt2 = n0 >> 8;                     // 256-wide W block index
    const unsigned bhalf = ((unsigned)(n0 >> 7) & 1u) * 16384u;

#if defined(__CUDA_ARCH_FEAT_SM103_ALL)
    const unsigned sb = smem_u32(sm_raw);
    const int warp = tid >> 5, lane = tid & 31;

    if (tid == 0) {
        MBARRIER_INIT(sb + 0, 1);      // empty
        MBARRIER_INIT(sb + 16, 1);     // done
        MBARRIER_INIT(sb + 24, 1);     // full (expect_tx)
    }
    if (tid >= 32 && tid < 40) ((float*)(sm_raw + 128))[tid - 32] = 0.f;  // sred
    if (warp == 4) {
        TCGEN05_ALLOC(sb + 64, 128);
        TCGEN05_RELINQ();
    }
    if (tid < 128) {
        float* sbias = (float*)(sm_raw + 1024);
        sbias[tid] = bias[n0 + tid];
    }
    __syncthreads();

    unsigned tmem;
    asm volatile("ld.shared.b32 %0, [%1];" : "=r"(tmem) : "r"(sb + 64));

    if (warp == 5) {
        // ---- producer: 4 bulk copies per chunk ----
        for (int c = 0; c < 16; c++) {
            MBARRIER_WAIT_PARITY(sb + 0, (unsigned)((c & 1) ^ 1));
            if (lane == 0) {
                const unsigned fb = sb + 24;
                MBARRIER_EXPECT_TX(fb, (unsigned)STAGE_BYTES);
                const unsigned st = sb + 2048;
                CP_BULK(st,         (const char*)Ahi + ((size_t)(mt * 16 + c) << 14), 16384u, fb);
                CP_BULK(st + 16384, (const char*)Alo + ((size_t)(mt * 16 + c) << 14), 16384u, fb);
                CP_BULK(st + 32768, (const char*)Bhi + (((size_t)(nt2 * 16 + c) << 15) + bhalf), 16384u, fb);
                CP_BULK(st + 49152, (const char*)Blo + (((size_t)(nt2 * 16 + c) << 15) + bhalf), 16384u, fb);
            }
        }
    } else if (warp == 4) {
        // ---- MMA warp ----
        for (int c = 0; c < 16; c++) {
            MBARRIER_WAIT_PARITY(sb + 24, (unsigned)(c & 1));
            if (lane == 0) {
                const unsigned st = sb + 2048;
                const unsigned long long dahi = sdesc(st);
                const unsigned long long dalo = sdesc(st + 16384);
                const unsigned long long dbhi = sdesc(st + 32768);
                const unsigned long long dblo = sdesc(st + 49152);
#pragma unroll
                for (int k = 0; k < 4; k++) {
                    const unsigned long long off = 2ull * k;
                    mma_f16_ss(tmem, dahi + off, dbhi + off, GEMM_IDESC,
                               (c == 0 && k == 0) ? 0u : 1u);
                    mma_f16_ss(tmem, dahi + off, dblo + off, GEMM_IDESC, 1u);
                    mma_f16_ss(tmem, dalo + off, dbhi + off, GEMM_IDESC, 1u);
                }
                TCGEN05_COMMIT(sb + 0);
            }
        }
        if (lane == 0) TCGEN05_COMMIT(sb + 16);
    }

    // ---- epilogue: all 192 threads, staged through smem for coalescing ----
    MBARRIER_WAIT_PARITY(sb + 16, 0);
    TCGEN05_FENCE_AFTER();
    const float* sbias = (const float*)(sm_raw + 1024);
    float* stage = (float*)(sm_raw + 2048);      // 128 x 33 fp32 (~16.9 KB)
    float* sred = (float*)(sm_raw + 128);        // 8 floats (GN partials)

    for (int cb = 0; cb < 4; cb++) {
        unsigned r[32];
        if (warp < 4) {
            TCGEN05_LD_32X32B_X32(r, tmem + cb * 32);
            TCGEN05_WAIT_LD();
            float* srow = stage + (warp * 32 + lane) * 33;
#pragma unroll
            for (int j = 0; j < 32; j++)
                srow[j] = __uint_as_float(r[j]) + sbias[cb * 32 + j];
        }
        __syncthreads();
        if (outKind == 0) {
            float ls = 0.f, lq = 0.f;
            for (int g = tid; g < 1024; g += GT) {
                const int row = g >> 3, cg = (g & 7) << 2;
                const float* s = stage + row * 33 + cg;
                float4 o = { s[0], s[1], s[2], s[3] };
                *(float4*)(C + (size_t)(m0 + row) * D_ + n0 + cb * 32 + cg) = o;
                ls += o.x + o.y + o.z + o.w;
                lq += o.x * o.x + o.y * o.y + o.z * o.z + o.w * o.w;
            }
#pragma unroll
            for (int off = 16; off; off >>= 1) {
                ls += __shfl_down_sync(0xffffffffu, ls, off);
                lq += __shfl_down_sync(0xffffffffu, lq, off);
            }
            if (lane == 0) {
                atomicAdd(sred + cb * 2, ls);
                atomicAdd(sred + cb * 2 + 1, lq);
            }
        } else if (outKind == 1) {
            for (int g = tid; g < 2048; g += GT) {
                const int row = g >> 4, cp = (g & 15) << 1;
                split_store2(Chi, Clo, (size_t)(m0 + row) * D_ + n0 + cb * 32 + cp,
                             stage[row * 33 + cp], stage[row * 33 + cp + 1]);
            }
        } else {
            for (int g = tid; g < 4096; g += GT) {
                const int col = g >> 7, row = g & 127;
                const float v = stage[row * 33 + col];
                __nv_bfloat16 hh = __float2bfloat16_rn(v);
                __nv_bfloat16 ll = __float2bfloat16_rn(v - __bfloat162float(hh));
                const size_t o = (size_t)(bb * 1024 + n0 + cb * 32 + col) * S_ + (m0 & (S_ - 1)) + row;
                Chi[o] = hh; Clo[o] = ll;
            }
        }
        __syncthreads();
    }
    if (outKind == 0 && tid < 2) {
        const float s = sred[(2 * tid) * 2] + sred[(2 * tid + 1) * 2];
        const float q = sred[(2 * tid) * 2 + 1] + sred[(2 * tid + 1) * 2 + 1];
        const int hg = (n0 >> 6) + tid;
        g_part[(bb * 16 + hg) * 16 + mchunk] = make_float2(s, q);
    }
    TCGEN05_FENCE_BEFORE();
    __syncthreads();
    if (warp == 4) TCGEN05_DEALLOC(tmem, 128);
#else
    for (int idx = tid; idx < 128 * 128; idx += GT) {
        const int i = idx >> 7, j = idx & 127;
        float acc = 0.f;
        for (int k = 0; k < D_; k++) {
            const float a = __bfloat162float(*(const __nv_bfloat16*)((const char*)Ahi + offA(m0 + i, k)))
                          + __bfloat162float(*(const __nv_bfloat16*)((const char*)Alo + offA(m0 + i, k)));
            const float w = __bfloat162float(*(const __nv_bfloat16*)((const char*)Bhi + offW(n0 + j, k)))
                          + __bfloat162float(*(const __nv_bfloat16*)((const char*)Blo + offW(n0 + j, k)));
            acc = fmaf(a, w, acc);
        }
        const float v = acc + bias[n0 + j];
        const int m = m0 + i;
        if (outKind == 1) {
            const size_t o = (size_t)m * D_ + n0 + j;
            __nv_bfloat16 h = __float2bfloat16_rn(v);
            Chi[o] = h;
            Clo[o] = __float2bfloat16_rn(v - __bfloat162float(h));
        } else if (outKind == 2) {
            const size_t o = (size_t)((m >> 11) * 1024 + n0 + j) * S_ + (m & (S_ - 1));
            __nv_bfloat16 h = __float2bfloat16_rn(v);
            Chi[o] = h;
            Clo[o] = __float2bfloat16_rn(v - __bfloat162float(h));
        } else {
            C[(size_t)m * D_ + n0 + j] = v;
            float* gp = (float*)&g_part[(bb * 16 + ((n0 + j) >> 6)) * 16 + mchunk];
            atomicAdd(gp, v);
            atomicAdd(gp + 1, v * v);
        }
    }
#endif
}

// ---------------- merged prep: W^T tiled split (z<4) + x tiled split (z==4) -
__global__ __launch_bounds__(256) void prep(
    const float* __restrict__ x,
    const float* __restrict__ W0, const float* __restrict__ W1,
    const float* __restrict__ W2, const float* __restrict__ W3)
{
    const int z = blockIdx.z;
    const int tx = threadIdx.x, ty = threadIdx.y;
    const int tid = ty * 32 + tx;
    if (z == 4) {
        if (blockIdx.x == 0 && blockIdx.y == 0) {
            for (int i = tid; i < 512; i += 256) g_part[i] = make_float2(0.f, 0.f);
        }
        const int u0 = (blockIdx.y * 32 + blockIdx.x) * 256 + tid;
#pragma unroll
        for (int r = 0; r < 4; r++) {
            const int i = (u0 + r * 262144) << 2;
            float4 v = *(const float4*)(x + i);
            const size_t o = offA(i >> 10, i & 1023);
            __nv_bfloat16 h0 = __float2bfloat16_rn(v.x);
            __nv_bfloat16 h1 = __float2bfloat16_rn(v.y);
            __nv_bfloat16 h2 = __float2bfloat16_rn(v.z);
            __nv_bfloat16 h3 = __float2bfloat16_rn(v.w);
            *(__nv_bfloat162*)((char*)g_xhi + o)     = __halves2bfloat162(h0, h1);
            *(__nv_bfloat162*)((char*)g_xhi + o + 4) = __halves2bfloat162(h2, h3);
            __nv_bfloat16 l0 = __float2bfloat16_rn(v.x - __bfloat162float(h0));
            __nv_bfloat16 l1 = __float2bfloat16_rn(v.y - __bfloat162float(h1));
            __nv_bfloat16 l2 = __float2bfloat16_rn(v.z - __bfloat162float(h2));
            __nv_bfloat16 l3 = __float2bfloat16_rn(v.w - __bfloat162float(h3));
            *(__nv_bfloat162*)((char*)g_xlo + o)     = __halves2bfloat162(l0, l1);
            *(__nv_bfloat162*)((char*)g_xlo + o + 4) = __halves2bfloat162(l2, l3);
        }
        return;
    }
    const float* W = (z == 0) ? W0 : (z == 1) ? W1 : (z == 2) ? W2 : W3;
    __nv_bfloat16* Hi = g_wthi[z];
    __nv_bfloat16* Lo = g_wtlo[z];
    __shared__ float t[32][33];
    const int n0 = blockIdx.x << 5, k0 = blockIdx.y << 5;
#pragma unroll
    for (int i = 0; i < 4; i++)
        t[ty + 8 * i][tx] = W[(size_t)(k0 + ty + 8 * i) * D_ + n0 + tx];
    __syncthreads();
#pragma unroll
    for (int i = 0; i < 4; i++) {
        const float v = t[tx][ty + 8 * i];
        __nv_bfloat16 h = __float2bfloat16_rn(v);
        __nv_bfloat16 l = __float2bfloat16_rn(v - __bfloat162float(h));
        const size_t o = offW(n0 + ty + 8 * i, k0 + tx);
        *(__nv_bfloat16*)((char*)Hi + o) = h;
        *(__nv_bfloat16*)((char*)Lo + o) = l;
    }
}

// ---------------- tcgen05 windowed decay attention ---------------------------
// CTA: 128 q rows x one (b,h). 256 threads, single KV stage, in-place S,
// TMEM 128 cols, 3 CTAs/SM. Epilogue writes g_a in GEMM-tiled layout.
#define ATT_IDESC 0x08100490u   // F32 acc, bf16, N=64, M=128
#define SO_BAR_S 0
#define SO_BAR_V 8
#define SO_TMEM  16
#define SO_TBL   1024
#define SO_QHI   3072
#define SO_QLO   (SO_QHI + 16384)
#define SO_KHI   (SO_QLO + 16384)        // 35840
#define SO_KLO   (SO_KHI + 8192)
#define SO_VHI   (SO_KLO + 8192)
#define SO_VLO   (SO_VHI + 8192)
#define ATT_SMEM (SO_VLO + 8192)         // 68608 bytes -> 3 CTAs/SM
// TMEM cols: O [0,64), S [64,128). Convert in-place: hi -> 64+, lo -> 96+.

__global__ __launch_bounds__(256, 3) void attn_tc()
{
    const int tid = threadIdx.x;
    const int bh = blockIdx.x;            // 0..31
    const int qp = 15 - blockIdx.y;       // heavy tiles first
    const int b = bh >> 4, h = bh & 15;
    const int qb = qp << 7;               // token base within batch
    const int qt0 = qp << 1;
    int jt0 = qt0 - WIN_TILES; if (jt0 < 0) jt0 = 0;
    const int nt = (qt0 + 1) - jt0 + 1;

#if defined(__CUDA_ARCH_FEAT_SM103_ALL)
    const unsigned sb = smem_u32(sm_raw);
    const int warp = tid >> 5, lane = tid & 31;
    const int sub = warp & 3;             // TMEM subpartition
    const int chalf = warp >> 2;          // column half (0/1)

    if (warp == 0) { TCGEN05_ALLOC(sb + SO_TMEM, 128); TCGEN05_RELINQ(); }
    if (tid == 0) {
        MBARRIER_INIT(sb + SO_BAR_S, 1);
        MBARRIER_INIT(sb + SO_BAR_V, 1);
    }
    float* tbl = (float*)(sm_raw + SO_TBL);
    for (int d = tid; d < 512; d += 256)
        tbl[d] = exp2f((float)d * LOG2DECAY);

    const char* kh0 = (const char*)(g_khi + ((size_t)(b * S_)) * D_ + h * HD_);
    const char* kl0 = (const char*)(g_klo + ((size_t)(b * S_)) * D_ + h * HD_);
    const char* vh0 = (const char*)(g_vthi + (size_t)bh * HD_ * S_);
    const char* vl0 = (const char*)(g_vtlo + (size_t)bh * HD_ * S_);

    // Q tiles: 128 rows x 128B, hi+lo
    {
        const char* qh = (const char*)(g_qhi + ((size_t)(b * S_ + qb)) * D_ + h * HD_);
        const char* ql = (const char*)(g_qlo + ((size_t)(b * S_ + qb)) * D_ + h * HD_);
        for (int g = tid; g < 1024; g += 256) {
            const int row = g >> 3, c = g & 7;
            const unsigned so = SWZ((unsigned)(row * 128 + c * 16));
            CP_ASYNC16(sb + SO_QHI + so, qh + (size_t)row * (D_ * 2) + c * 16);
            CP_ASYNC16(sb + SO_QLO + so, ql + (size_t)row * (D_ * 2) + c * 16);
        }
    }
    CP_COMMIT();
    __syncthreads();

    unsigned tmem;
    asm volatile("ld.shared.b32 %0, [%1];" : "=r"(tmem) : "r"(sb + SO_TMEM));

    const unsigned long long dQhi = sdesc(sb + SO_QHI), dQlo = sdesc(sb + SO_QLO);
    const unsigned long long dKhi = sdesc(sb + SO_KHI), dKlo = sdesc(sb + SO_KLO);
    const unsigned long long dVhi = sdesc(sb + SO_VHI), dVlo = sdesc(sb + SO_VLO);

    unsigned phs = 0, phv = 0;
    const int qrow = qb + sub * 32 + lane;                 // q token within batch

    for (int it = 0; it < nt; it++) {
        const int jt = jt0 + it;

        // V-MMA(it-1) must finish before KV smem / S cols are reused
        if (it > 0) { MBARRIER_WAIT_PARITY(sb + SO_BAR_V, phv); phv ^= 1; }

        // load KV(it)
        {
            const size_t koff = (size_t)(jt << 6);
            for (int g = tid; g < 512; g += 256) {
                const int row = g >> 3, c = g & 7;
                const unsigned so = SWZ((unsigned)(row * 128 + c * 16));
                CP_ASYNC16(sb + SO_KHI + so, kh0 + (koff + row) * (D_ * 2) + c * 16);
                CP_ASYNC16(sb + SO_KLO + so, kl0 + (koff + row) * (D_ * 2) + c * 16);
                CP_ASYNC16(sb + SO_VHI + so, vh0 + ((size_t)row * S_ + (jt << 6)) * 2 + c * 16);
                CP_ASYNC16(sb + SO_VLO + so, vl0 + ((size_t)row * S_ + (jt << 6)) * 2 + c * 16);
            }
            CP_COMMIT();
        }
        CP_WAIT0();
        FENCE_PROXY_ASYNC();
        __syncthreads();

        // S = Q K^T  (S at tmem+64, fp32)
        if (tid == 0) {
#pragma unroll
            for (int k = 0; k < 4; k++) {
                const unsigned long long off = 2ull * k;
                mma_f16_ss(tmem + 64, dQhi + off, dKhi + off, ATT_IDESC, k > 0 ? 1u : 0u);
                mma_f16_ss(tmem + 64, dQhi + off, dKlo + off, ATT_IDESC, 1u);
                mma_f16_ss(tmem + 64, dQlo + off, dKhi + off, ATT_IDESC, 1u);
            }
            TCGEN05_COMMIT(sb + SO_BAR_S);
        }
        MBARRIER_WAIT_PARITY(sb + SO_BAR_S, phs); phs ^= 1;
        TCGEN05_FENCE_AFTER();

        // convert: read S fp32, mask, split -> write back IN PLACE as bf16x2
        const int kbase = jt << 6;
        {
            unsigned r[32];
            TCGEN05_LD_32X32B_X32(r, tmem + 64 + chalf * 32);
            TCGEN05_WAIT_LD();
            __syncthreads();             // ALL reads complete before any write
#pragma unroll
            for (int half = 0; half < 2; half++) {
                unsigned hi8[8], lo8[8];
#pragma unroll
                for (int c = 0; c < 16; c += 2) {
                    const int col = chalf * 32 + half * 16 + c;
                    const int d0 = qrow - (kbase + col);
                    const int d1 = d0 - 1;
                    const float f0 = (d0 >= 0) ? tbl[d0] : 0.f;
                    const float f1 = (d1 >= 0) ? tbl[d1] : 0.f;
                    const float v0 = __uint_as_float(r[half * 16 + c]) * f0;
                    const float v1 = __uint_as_float(r[half * 16 + c + 1]) * f1;
                    __nv_bfloat16 h0 = __float2bfloat16_rn(v0);
                    __nv_bfloat16 h1 = __float2bfloat16_rn(v1);
                    __nv_bfloat16 l0 = __float2bfloat16_rn(v0 - __bfloat162float(h0));
                    __nv_bfloat16 l1 = __float2bfloat16_rn(v1 - __bfloat162float(h1));
                    __nv_bfloat162 ph = __halves2bfloat162(h0, h1);
                    __nv_bfloat162 pl = __halves2bfloat162(l0, l1);
                    hi8[c >> 1] = *reinterpret_cast<unsigned*>(&ph);
                    lo8[c >> 1] = *reinterpret_cast<unsigned*>(&pl);
                }
                const unsigned cbase = (unsigned)(chalf * 16 + half * 8);
                TCGEN05_ST_32X32B_X8(tmem + 64 + cbase, hi8);
                TCGEN05_ST_32X32B_X8(tmem + 96 + cbase, lo8);
            }
            TCGEN05_WAIT_ST();
        }
        TCGEN05_FENCE_BEFORE();
        __syncthreads();

        // O += S V  (TS: A = S bf16 in TMEM, B = V^T in smem)
        if (tid == 0) {
            TCGEN05_FENCE_AFTER();
#pragma unroll
            for (int k = 0; k < 4; k++) {
                const unsigned long long off = 2ull * k;
                mma_f16_ts(tmem, tmem + 64 + k * 8, dVhi + off, ATT_IDESC,
                           (it == 0 && k == 0) ? 0u : 1u);
                mma_f16_ts(tmem, tmem + 64 + k * 8, dVlo + off, ATT_IDESC, 1u);
                mma_f16_ts(tmem, tmem + 96 + k * 8, dVhi + off, ATT_IDESC, 1u);
            }
            TCGEN05_COMMIT(sb + SO_BAR_V);
        }
    }
    MBARRIER_WAIT_PARITY(sb + SO_BAR_V, phv);
    TCGEN05_FENCE_AFTER();

    // epilogue: O -> smem (stride-65) -> g_a in GEMM-tiled swizzled layout
    {
        float* stg = (float*)(sm_raw + SO_QHI);   // 33 KB in dead Q/K region
        unsigned r[32];
        TCGEN05_LD_32X32B_X32(r, tmem + chalf * 32);
        TCGEN05_WAIT_LD();
        float* srow = stg + (sub * 32 + lane) * 65 + chalf * 32;
#pragma unroll
        for (int j = 0; j < 32; j++) srow[j] = __uint_as_float(r[j]);
        TCGEN05_FENCE_BEFORE();
        __syncthreads();
        const size_t abase = ((size_t)((((b * S_) + qb) >> 7) * 16 + h)) << 14;
        for (int g = tid; g < 4096; g += 256) {
            const int row = g >> 5, cp = (g & 31) << 1;
            const size_t o = abase + SWZ((unsigned)(row * 128 + ((cp >> 3) << 4))) + ((cp & 7) << 1);
            const float v0 = stg[row * 65 + cp], v1 = stg[row * 65 + cp + 1];
            __nv_bfloat16 h0 = __float2bfloat16_rn(v0);
            __nv_bfloat16 h1 = __float2bfloat16_rn(v1);
            __nv_bfloat16 l0 = __float2bfloat16_rn(v0 - __bfloat162float(h0));
            __nv_bfloat16 l1 = __float2bfloat16_rn(v1 - __bfloat162float(h1));
            *(__nv_bfloat162*)((char*)g_ahi + o) = __halves2bfloat162(h0, h1);
            *(__nv_bfloat162*)((char*)g_alo + o) = __halves2bfloat162(l0, l1);
        }
    }
    __syncthreads();
    if (warp == 0) TCGEN05_DEALLOC(tmem, 128);
#else
    // -------- correct (very slow) fallback: never runs on GB300 -------------
    const int jlo = jt0 << 6;
    for (int e = tid; e < 128 * HD_; e += 256) {
        const int i = e >> 6, d = e & 63;
        const int qr = qb + i;
        float acc = 0.f;
        for (int j = jlo; j <= qr; j++) {
            float s = 0.f;
            const size_t qo = (size_t)(b * S_ + qr) * D_ + h * HD_;
            const size_t ko = (size_t)(b * S_ + j) * D_ + h * HD_;
            for (int k = 0; k < HD_; k++) {
                const float qv = __bfloat162float(g_qhi[qo + k]) + __bfloat162float(g_qlo[qo + k]);
                const float kv = __bfloat162float(g_khi[ko + k]) + __bfloat162float(g_klo[ko + k]);
                s = fmaf(qv, kv, s);
            }
            const float f = exp2f((float)(qr - j) * LOG2DECAY);
            const size_t vo = (size_t)(bh * HD_ + d) * S_ + j;
            const float vv = __bfloat162float(g_vthi[vo]) + __bfloat162float(g_vtlo[vo]);
            acc = fmaf(s * f, vv, acc);
        }
        const size_t o = offA(b * S_ + qr, h * HD_ + d);
        __nv_bfloat16 hh = __float2bfloat16_rn(acc);
        *(__nv_bfloat16*)((char*)g_ahi + o) = hh;
        *(__nv_bfloat16*)((char*)g_alo + o) =
            __float2bfloat16_rn(acc - __bfloat162float(hh));
    }
#endif
}

// ---------------- GroupNorm (partials fused into proj epilogue) -------------
__global__ void gn_stats()
{
    const int g = threadIdx.x;
    float s = 0.f, q = 0.f;
    for (int c = 0; c < 16; c++) {
        float2 p = g_part[g * 16 + c];
        s += p.x; q += p.y;
    }
    const float n = (float)(S_ * HD_);
    const float mu = s / n;
    const float var = q / n - mu * mu;
    g_stats[g] = make_float2(mu, rsqrtf(var + 1e-5f));
}

__global__ __launch_bounds__(256) void gn_apply(
    const float* __restrict__ gamma, const float* __restrict__ beta,
    float* __restrict__ out)
{
    const int t = blockIdx.x * 256 + threadIdx.x;
    const int base = t << 2;
    const int d = base & (D_ - 1);
    const int row = base >> 10;
    const int b = row >> 11;
    const float2 st = g_stats[(b << 4) | (d >> 6)];
    const float4 v  = *(const float4*)(g_proj + base);
    const float4 gm = *(const float4*)(gamma + d);
    const float4 bt = *(const float4*)(beta + d);
    float4 o;
    o.x = (v.x - st.x) * st.y * gm.x + bt.x;
    o.y = (v.y - st.x) * st.y * gm.y + bt.y;
    o.z = (v.z - st.x) * st.y * gm.z + bt.z;
    o.w = (v.w - st.x) * st.y * gm.w + bt.w;
    *(float4*)(out + base) = o;
}

// ---------------- launch ----------------------------------------------------
extern "C" void kernel_launch(void* const* d_in, const int* in_sizes, int n_in,
                              void* d_out, int out_size)
{
    (void)in_sizes; (void)n_in; (void)out_size;
    const float* x     = (const float*)d_in[0];
    const float* Wq    = (const float*)d_in[1];
    const float* bq    = (const float*)d_in[2];
    const float* Wk    = (const float*)d_in[3];
    const float* bk    = (const float*)d_in[4];
    const float* Wv    = (const float*)d_in[5];
    const float* bv    = (const float*)d_in[6];
    const float* Wo    = (const float*)d_in[7];
    const float* bo    = (const float*)d_in[8];
    const float* gamma = (const float*)d_in[9];
    const float* beta  = (const float*)d_in[10];
    float* out = (float*)d_out;

    cudaFuncSetAttribute(gemm_tc,
                         cudaFuncAttributeMaxDynamicSharedMemorySize, DYN_SMEM);
    cudaFuncSetAttribute(attn_tc,
                         cudaFuncAttributeMaxDynamicSharedMemorySize, ATT_SMEM);

    prep<<<dim3(32, 32, 5), dim3(32, 8)>>>(x, Wq, Wk, Wv, Wo);
    gemm_tc<<<dim3(8, 32, 3), GT, DYN_SMEM>>>(0, bq, bk, bv, bo);
    attn_tc<<<dim3(32, 16), 256, ATT_SMEM>>>();
    gemm_tc<<<dim3(8, 32, 1), GT, DYN_SMEM>>>(1, bq, bk, bv, bo);
    gn_stats<<<1, 32>>>();
    gn_apply<<<(M_ * D_) / (256 * 4), 256>>>(gamma, beta, out);
}

// round 16
// speedup vs baseline: 1.1272x; 1.0359x over previous
#include <cuda_runtime.h>
#include <cuda_bf16.h>
#include <cstdint>

#define B_  2
#define S_  2048
#define D_  1024
#define H_  16
#define HD_ 64
#define M_  (B_ * S_)          // 4096 rows

#define WIN_TILES 4            // 256-key decay window: 0.95^256 ~ 2e-6
#define LOG2DECAY -0.07400058144377693f

// ---------------- scratch (device globals: no allocation allowed) ----------
__device__ float  g_proj[M_ * D_];
__device__ float2 g_part[32 * 16];
__device__ float2 g_stats[32];

// GEMM operands stored PRE-TILED + PRE-SWIZZLED (smem image blocks):
//   A-type  (x, a): block (mtile*16 + chunk) of 16384 B = 128 rows x 128 B
//   W-type  (W^T) : block (ntile*16 + chunk) of 32768 B = 256 rows x 128 B
__device__ __align__(128) __nv_bfloat16 g_xhi[M_ * D_];
__device__ __align__(128) __nv_bfloat16 g_xlo[M_ * D_];
__device__ __align__(128) __nv_bfloat16 g_qhi[M_ * D_];
__device__ __align__(128) __nv_bfloat16 g_qlo[M_ * D_];
__device__ __align__(128) __nv_bfloat16 g_khi[M_ * D_];
__device__ __align__(128) __nv_bfloat16 g_klo[M_ * D_];
__device__ __align__(128) __nv_bfloat16 g_vthi[B_ * H_ * HD_ * S_];  // [b*1024+n][t]
__device__ __align__(128) __nv_bfloat16 g_vtlo[B_ * H_ * HD_ * S_];
__device__ __align__(128) __nv_bfloat16 g_ahi[M_ * D_];              // tiled
__device__ __align__(128) __nv_bfloat16 g_alo[M_ * D_];              // tiled
__device__ __align__(128) __nv_bfloat16 g_wthi[4][D_ * D_];          // tiled
__device__ __align__(128) __nv_bfloat16 g_wtlo[4][D_ * D_];          // tiled

extern __shared__ unsigned char sm_raw[];

#define SWZ(o) ((o) ^ (((o) >> 3) & 0x70))

// byte offset of element (m,k) in A-type tiled array
__device__ __forceinline__ size_t offA(int m, int k) {
    const int kc = k & 63;
    const unsigned w = SWZ((unsigned)((m & 127) * 128 + ((kc >> 3) << 4)));
    return (((size_t)((m >> 7) * 16 + (k >> 6))) << 14) + w + ((kc & 7) << 1);
}
// byte offset of element (n,k) in W-type tiled array
__device__ __forceinline__ size_t offW(int n, int k) {
    const int kc = k & 63;
    const unsigned w = SWZ((unsigned)((n & 255) * 128 + ((kc >> 3) << 4)));
    return (((size_t)((n >> 8) * 16 + (k >> 6))) << 15) + w + ((kc & 7) << 1);
}

// ---------------- PTX helpers ----------------------------------------------
__device__ __forceinline__ unsigned smem_u32(const void* p) {
    unsigned r;
    asm("{ .reg .u64 t; cvta.to.shared.u64 t, %1; cvt.u32.u64 %0, t; }"
        : "=r"(r) : "l"(p));
    return r;
}

#define MBARRIER_INIT(addr, cnt) \
    asm volatile("mbarrier.init.shared.b64 [%0], %1;" :: "r"(addr), "r"(cnt) : "memory")

#define MBARRIER_WAIT_PARITY(addr, ph) do {                                     \
    unsigned _m = (addr), _p = (ph), _d;                                        \
    asm volatile("{\n\t.reg .pred p;\n\t"                                       \
        "mbarrier.try_wait.parity.acquire.cta.shared::cta.b64 p, [%1], %2;\n\t" \
        "selp.b32 %0, 1, 0, p;\n\t}"                                            \
        : "=r"(_d) : "r"(_m), "r"(_p) : "memory");                              \
    if (!_d) {                                                                  \
        asm volatile("{\n\t.reg .pred P1;\n\t"                                  \
            "WL_%=:\n\t"                                                        \
            "mbarrier.try_wait.parity.acquire.cta.shared::cta.b64 P1, [%0], %1, 0x989680;\n\t" \
            "@P1 bra.uni WD_%=;\n\t"                                            \
            "bra.uni WL_%=;\n\t"                                                \
            "WD_%=:\n\t}"                                                       \
            :: "r"(_m), "r"(_p) : "memory");                                    \
    }                                                                           \
} while (0)

#define MBARRIER_EXPECT_TX(addr, tx) \
    asm volatile("mbarrier.arrive.expect_tx.shared.b64 _, [%0], %1;" \
                 :: "r"(addr), "r"(tx) : "memory")

#define CP_ASYNC16(dst, src) \
    asm volatile("cp.async.cg.shared.global [%0], [%1], 16;" :: "r"(dst), "l"(src))
#define CP_COMMIT() asm volatile("cp.async.commit_group;" ::: "memory")
#define CP_WAIT0()  asm volatile("cp.async.wait_group 0;" ::: "memory")
#define CP_BULK(dst, src, bytes, mbar) \
    asm volatile("cp.async.bulk.shared::cluster.global.mbarrier::complete_tx::bytes " \
                 "[%0], [%1], %2, [%3];" \
                 :: "r"(dst), "l"(src), "r"(bytes), "r"(mbar) : "memory")
#define FENCE_PROXY_ASYNC() asm volatile("fence.proxy.async.shared::cta;" ::: "memory")

__device__ __forceinline__ void split_store2(
    __nv_bfloat16* hi, __nv_bfloat16* lo, size_t idx, float v0, float v1)
{
    __nv_bfloat16 h0 = __float2bfloat16_rn(v0);
    __nv_bfloat16 h1 = __float2bfloat16_rn(v1);
    __nv_bfloat16 l0 = __float2bfloat16_rn(v0 - __bfloat162float(h0));
    __nv_bfloat16 l1 = __float2bfloat16_rn(v1 - __bfloat162float(h1));
    *(__nv_bfloat162*)(hi + idx) = __halves2bfloat162(h0, h1);
    *(__nv_bfloat162*)(lo + idx) = __halves2bfloat162(l0, l1);
}

#if defined(__CUDA_ARCH_FEAT_SM103_ALL)

#define TCGEN05_ALLOC(saddr, n) \
    asm volatile("tcgen05.alloc.cta_group::1.sync.aligned.shared::cta.b32 [%0], %1;" \
                 :: "r"(saddr), "r"(n) : "memory")
#define TCGEN05_DEALLOC(t, n) \
    asm volatile("tcgen05.dealloc.cta_group::1.sync.aligned.b32 %0, %1;" :: "r"(t), "r"(n))
#define TCGEN05_RELINQ() \
    asm volatile("tcgen05.relinquish_alloc_permit.cta_group::1.sync.aligned;")
#define TCGEN05_COMMIT(bar) \
    asm volatile("tcgen05.commit.cta_group::1.mbarrier::arrive::one.shared::cluster.b64 [%0];" \
                 :: "r"(bar) : "memory")
#define TCGEN05_FENCE_AFTER() \
    asm volatile("tcgen05.fence::after_thread_sync;" ::: "memory")
#define TCGEN05_FENCE_BEFORE() \
    asm volatile("tcgen05.fence::before_thread_sync;" ::: "memory")
#define TCGEN05_WAIT_LD() \
    asm volatile("tcgen05.wait::ld.sync.aligned;" ::: "memory")
#define TCGEN05_WAIT_ST() \
    asm volatile("tcgen05.wait::st.sync.aligned;" ::: "memory")

#define TCGEN05_LD_32X32B_X32(r, tmem_addr) \
    asm volatile( \
        "tcgen05.ld.sync.aligned.32x32b.x32.b32 " \
        "{%0, %1, %2, %3, %4, %5, %6, %7, " \
        " %8, %9, %10, %11, %12, %13, %14, %15, " \
        " %16, %17, %18, %19, %20, %21, %22, %23, " \
        " %24, %25, %26, %27, %28, %29, %30, %31}, [%32];" \
        : "=r"((r)[0]),  "=r"((r)[1]),  "=r"((r)[2]),  "=r"((r)[3]), \
          "=r"((r)[4]),  "=r"((r)[5]),  "=r"((r)[6]),  "=r"((r)[7]), \
          "=r"((r)[8]),  "=r"((r)[9]),  "=r"((r)[10]), "=r"((r)[11]), \
          "=r"((r)[12]), "=r"((r)[13]), "=r"((r)[14]), "=r"((r)[15]), \
          "=r"((r)[16]), "=r"((r)[17]), "=r"((r)[18]), "=r"((r)[19]), \
          "=r"((r)[20]), "=r"((r)[21]), "=r"((r)[22]), "=r"((r)[23]), \
          "=r"((r)[24]), "=r"((r)[25]), "=r"((r)[26]), "=r"((r)[27]), \
          "=r"((r)[28]), "=r"((r)[29]), "=r"((r)[30]), "=r"((r)[31]) \
        : "r"(tmem_addr))

#define TCGEN05_ST_32X32B_X8(tmem_addr, r) \
    asm volatile( \
        "tcgen05.st.sync.aligned.32x32b.x8.b32 [%0], " \
        "{%1, %2, %3, %4, %5, %6, %7, %8};" \
        :: "r"(tmem_addr), \
           "r"((r)[0]), "r"((r)[1]), "r"((r)[2]), "r"((r)[3]), \
           "r"((r)[4]), "r"((r)[5]), "r"((r)[6]), "r"((r)[7]) \
        : "memory")

__device__ __forceinline__ void mma_f16_ss(
    unsigned d_tmem, unsigned long long a_desc, unsigned long long b_desc,
    unsigned idesc, unsigned enable)
{
    asm volatile(
        "{\n\t.reg .pred p;\n\t"
        "setp.ne.u32 p, %4, 0;\n\t"
        "tcgen05.mma.cta_group::1.kind::f16 [%0], %1, %2, %3, {%5, %5, %5, %5}, p;\n\t"
        "}"
        :: "r"(d_tmem), "l"(a_desc), "l"(b_desc), "r"(idesc), "r"(enable), "r"(0u)
        : "memory");
}

__device__ __forceinline__ void mma_f16_ts(
    unsigned d_tmem, unsigned a_tmem, unsigned long long b_desc,
    unsigned idesc, unsigned enable)
{
    asm volatile(
        "{\n\t.reg .pred p;\n\t"
        "setp.ne.u32 p, %4, 0;\n\t"
        "tcgen05.mma.cta_group::1.kind::f16 [%0], [%1], %2, %3, {%5, %5, %5, %5}, p;\n\t"
        "}"
        :: "r"(d_tmem), "r"(a_tmem), "l"(b_desc), "r"(idesc), "r"(enable), "r"(0u)
        : "memory");
}

__device__ __forceinline__ unsigned long long sdesc(unsigned addr) {
    // SW128, Blackwell version=1, LBO=1, SBO=64
    return 0x4000404000010000ull | ((unsigned long long)(addr >> 4) & 0x3FFF);
}

#endif  // __CUDA_ARCH_FEAT_SM103_ALL

// ============ GEMM variant A: 128x128 tile, 1 stage, 3 CTAs/SM (qkv) =======
#define IDESC128 0x08200490u   // F32 acc, bf16 a/b, N=128, M=128
#define STG128 65536
#define DSM128 (2048 + STG128)
#define GT 192

__global__ __launch_bounds__(GT, 3) void gemm_tc128(
    const float* __restrict__ bq, const float* __restrict__ bk,
    const float* __restrict__ bv)
{
    const int tid = threadIdx.x;
    const int n0 = blockIdx.x << 7;     // 0..896
    const int m0 = blockIdx.y << 7;     // 0..3968
    const int z = blockIdx.z;

    const __nv_bfloat16 *Bhi = g_wthi[z], *Blo = g_wtlo[z];
    const float* bias = (z == 0) ? bq : (z == 1) ? bk : bv;
    __nv_bfloat16 *Chi, *Clo;
    int outKind;   // 1 = split hi/lo, 2 = V^T split
    if (z == 0)      { Chi = g_qhi; Clo = g_qlo; outKind = 1; }
    else if (z == 1) { Chi = g_khi; Clo = g_klo; outKind = 1; }
    else             { Chi = g_vthi; Clo = g_vtlo; outKind = 2; }
    const int bb = m0 >> 11;
    const int mt = m0 >> 7;
    const int nt2 = n0 >> 8;
    const unsigned bhalf = ((unsigned)(n0 >> 7) & 1u) * 16384u;

#if defined(__CUDA_ARCH_FEAT_SM103_ALL)
    const unsigned sb = smem_u32(sm_raw);
    const int warp = tid >> 5, lane = tid & 31;

    if (tid == 0) {
        MBARRIER_INIT(sb + 0, 1);      // empty
        MBARRIER_INIT(sb + 16, 1);     // done
        MBARRIER_INIT(sb + 24, 1);     // full (expect_tx)
    }
    if (warp == 4) { TCGEN05_ALLOC(sb + 64, 128); TCGEN05_RELINQ(); }
    if (tid < 128) ((float*)(sm_raw + 1024))[tid] = bias[n0 + tid];
    __syncthreads();

    unsigned tmem;
    asm volatile("ld.shared.b32 %0, [%1];" : "=r"(tmem) : "r"(sb + 64));

    if (warp == 5) {
        for (int c = 0; c < 16; c++) {
            MBARRIER_WAIT_PARITY(sb + 0, (unsigned)((c & 1) ^ 1));
            if (lane == 0) {
                const unsigned fb = sb + 24;
                MBARRIER_EXPECT_TX(fb, (unsigned)STG128);
                const unsigned st = sb + 2048;
                CP_BULK(st,         (const char*)g_xhi + ((size_t)(mt * 16 + c) << 14), 16384u, fb);
                CP_BULK(st + 16384, (const char*)g_xlo + ((size_t)(mt * 16 + c) << 14), 16384u, fb);
                CP_BULK(st + 32768, (const char*)Bhi + (((size_t)(nt2 * 16 + c) << 15) + bhalf), 16384u, fb);
                CP_BULK(st + 49152, (const char*)Blo + (((size_t)(nt2 * 16 + c) << 15) + bhalf), 16384u, fb);
            }
        }
    } else if (warp == 4) {
        for (int c = 0; c < 16; c++) {
            MBARRIER_WAIT_PARITY(sb + 24, (unsigned)(c & 1));
            if (lane == 0) {
                const unsigned st = sb + 2048;
                const unsigned long long dahi = sdesc(st);
                const unsigned long long dalo = sdesc(st + 16384);
                const unsigned long long dbhi = sdesc(st + 32768);
                const unsigned long long dblo = sdesc(st + 49152);
#pragma unroll
                for (int k = 0; k < 4; k++) {
                    const unsigned long long off = 2ull * k;
                    mma_f16_ss(tmem, dahi + off, dbhi + off, IDESC128,
                               (c == 0 && k == 0) ? 0u : 1u);
                    mma_f16_ss(tmem, dahi + off, dblo + off, IDESC128, 1u);
                    mma_f16_ss(tmem, dalo + off, dbhi + off, IDESC128, 1u);
                }
                TCGEN05_COMMIT(sb + 0);
            }
        }
        if (lane == 0) TCGEN05_COMMIT(sb + 16);
    }

    MBARRIER_WAIT_PARITY(sb + 16, 0);
    TCGEN05_FENCE_AFTER();
    const float* sbias = (const float*)(sm_raw + 1024);
    float* stage = (float*)(sm_raw + 2048);

    for (int cb = 0; cb < 4; cb++) {
        unsigned r[32];
        if (warp < 4) {
            TCGEN05_LD_32X32B_X32(r, tmem + cb * 32);
            TCGEN05_WAIT_LD();
            float* srow = stage + (warp * 32 + lane) * 33;
#pragma unroll
            for (int j = 0; j < 32; j++)
                srow[j] = __uint_as_float(r[j]) + sbias[cb * 32 + j];
        }
        __syncthreads();
        if (outKind == 1) {
            for (int g = tid; g < 2048; g += GT) {
                const int row = g >> 4, cp = (g & 15) << 1;
                split_store2(Chi, Clo, (size_t)(m0 + row) * D_ + n0 + cb * 32 + cp,
                             stage[row * 33 + cp], stage[row * 33 + cp + 1]);
            }
        } else {
            for (int g = tid; g < 4096; g += GT) {
                const int col = g >> 7, row = g & 127;
                const float v = stage[row * 33 + col];
                __nv_bfloat16 hh = __float2bfloat16_rn(v);
                __nv_bfloat16 ll = __float2bfloat16_rn(v - __bfloat162float(hh));
                const size_t o = (size_t)(bb * 1024 + n0 + cb * 32 + col) * S_ + (m0 & (S_ - 1)) + row;
                Chi[o] = hh; Clo[o] = ll;
            }
        }
        __syncthreads();
    }
    TCGEN05_FENCE_BEFORE();
    __syncthreads();
    if (warp == 4) TCGEN05_DEALLOC(tmem, 128);
#else
    for (int idx = tid; idx < 128 * 128; idx += GT) {
        const int i = idx >> 7, j = idx & 127;
        float acc = 0.f;
        for (int k = 0; k < D_; k++) {
            const float a = __bfloat162float(*(const __nv_bfloat16*)((const char*)g_xhi + offA(m0 + i, k)))
                          + __bfloat162float(*(const __nv_bfloat16*)((const char*)g_xlo + offA(m0 + i, k)));
            const float w = __bfloat162float(*(const __nv_bfloat16*)((const char*)Bhi + offW(n0 + j, k)))
                          + __bfloat162float(*(const __nv_bfloat16*)((const char*)Blo + offW(n0 + j, k)));
            acc = fmaf(a, w, acc);
        }
        const float v = acc + bias[n0 + j];
        const int m = m0 + i;
        if (outKind == 1) {
            const size_t o = (size_t)m * D_ + n0 + j;
            __nv_bfloat16 h = __float2bfloat16_rn(v);
            Chi[o] = h;
            Clo[o] = __float2bfloat16_rn(v - __bfloat162float(h));
        } else {
            const size_t o = (size_t)((m >> 11) * 1024 + n0 + j) * S_ + (m & (S_ - 1));
            __nv_bfloat16 h = __float2bfloat16_rn(v);
            Chi[o] = h;
            Clo[o] = __float2bfloat16_rn(v - __bfloat162float(h));
        }
    }
#endif
}

// ============ GEMM variant B: 128x256 tile, 2 stages (proj) ================
#define IDESC256 0x08400490u   // F32 acc, bf16 a/b, N=256, M=128
#define STG256 98304
#define DSM256 (2048 + 2 * STG256)

__global__ __launch_bounds__(GT, 1) void gemm_tc256(const float* __restrict__ bo)
{
    const int tid = threadIdx.x;
    const int n0 = blockIdx.x << 8;     // 0..768
    const int m0 = blockIdx.y << 7;     // 0..3968
    const int bb = m0 >> 11;
    const int mchunk = (m0 & (S_ - 1)) >> 7;
    const int mt = m0 >> 7, nt = n0 >> 8;
    const __nv_bfloat16 *Bhi = g_wthi[3], *Blo = g_wtlo[3];
    float* C = g_proj;

#if defined(__CUDA_ARCH_FEAT_SM103_ALL)
    const unsigned sb = smem_u32(sm_raw);
    const int warp = tid >> 5, lane = tid & 31;

    if (tid == 0) {
        MBARRIER_INIT(sb + 0, 1);      // empty0
        MBARRIER_INIT(sb + 8, 1);      // empty1
        MBARRIER_INIT(sb + 16, 1);     // done
        MBARRIER_INIT(sb + 24, 1);     // full0
        MBARRIER_INIT(sb + 32, 1);     // full1
    }
    if (tid >= 32 && tid < 48) ((float*)(sm_raw + 128))[tid - 32] = 0.f;  // sred
    if (warp == 4) { TCGEN05_ALLOC(sb + 64, 256); TCGEN05_RELINQ(); }
    if (tid < 128) {
        float* sbias = (float*)(sm_raw + 1024);
        sbias[tid] = bo[n0 + tid];
        sbias[tid + 128] = bo[n0 + 128 + tid];
    }
    __syncthreads();

    unsigned tmem;
    asm volatile("ld.shared.b32 %0, [%1];" : "=r"(tmem) : "r"(sb + 64));

    if (warp == 5) {
        for (int c = 0; c < 16; c++) {
            const int s = c & 1, u = c >> 1;
            MBARRIER_WAIT_PARITY(sb + s * 8, (unsigned)((u & 1) ^ 1));
            if (lane == 0) {
                const unsigned fb = sb + 24 + s * 8;
                MBARRIER_EXPECT_TX(fb, (unsigned)STG256);
                const unsigned st = sb + 2048 + s * STG256;
                CP_BULK(st,         (const char*)g_ahi + ((size_t)(mt * 16 + c) << 14), 16384u, fb);
                CP_BULK(st + 16384, (const char*)g_alo + ((size_t)(mt * 16 + c) << 14), 16384u, fb);
                CP_BULK(st + 32768, (const char*)Bhi + ((size_t)(nt * 16 + c) << 15), 32768u, fb);
                CP_BULK(st + 65536, (const char*)Blo + ((size_t)(nt * 16 + c) << 15), 32768u, fb);
            }
        }
    } else if (warp == 4) {
        for (int c = 0; c < 16; c++) {
            const int s = c & 1, u = c >> 1;
            MBARRIER_WAIT_PARITY(sb + 24 + s * 8, (unsigned)(u & 1));
            if (lane == 0) {
                const unsigned st = sb + 2048 + s * STG256;
                const unsigned long long dahi = sdesc(st);
                const unsigned long long dalo = sdesc(st + 16384);
                const unsigned long long dbhi = sdesc(st + 32768);
                const unsigned long long dblo = sdesc(st + 65536);
#pragma unroll
                for (int k = 0; k < 4; k++) {
                    const unsigned long long off = 2ull * k;
                    mma_f16_ss(tmem, dahi + off, dbhi + off, IDESC256,
                               (c == 0 && k == 0) ? 0u : 1u);
                    mma_f16_ss(tmem, dahi + off, dblo + off, IDESC256, 1u);
                    mma_f16_ss(tmem, dalo + off, dbhi + off, IDESC256, 1u);
                }
                TCGEN05_COMMIT(sb + s * 8);
            }
        }
        if (lane == 0) TCGEN05_COMMIT(sb + 16);
    }

    MBARRIER_WAIT_PARITY(sb + 16, 0);
    TCGEN05_FENCE_AFTER();
    const float* sbias = (const float*)(sm_raw + 1024);
    float* stage = (float*)(sm_raw + 2048);
    float* sred = (float*)(sm_raw + 128);

    for (int cb = 0; cb < 8; cb++) {
        unsigned r[32];
        if (warp < 4) {
            TCGEN05_LD_32X32B_X32(r, tmem + cb * 32);
            TCGEN05_WAIT_LD();
            float* srow = stage + (warp * 32 + lane) * 33;
#pragma unroll
            for (int j = 0; j < 32; j++)
                srow[j] = __uint_as_float(r[j]) + sbias[cb * 32 + j];
        }
        __syncthreads();
        float ls = 0.f, lq = 0.f;
        for (int g = tid; g < 1024; g += GT) {
            const int row = g >> 3, cg = (g & 7) << 2;
            const float* s = stage + row * 33 + cg;
            float4 o = { s[0], s[1], s[2], s[3] };
            *(float4*)(C + (size_t)(m0 + row) * D_ + n0 + cb * 32 + cg) = o;
            ls += o.x + o.y + o.z + o.w;
            lq += o.x * o.x + o.y * o.y + o.z * o.z + o.w * o.w;
        }
#pragma unroll
        for (int off = 16; off; off >>= 1) {
            ls += __shfl_down_sync(0xffffffffu, ls, off);
            lq += __shfl_down_sync(0xffffffffu, lq, off);
        }
        if (lane == 0) {
            atomicAdd(sred + cb * 2, ls);
            atomicAdd(sred + cb * 2 + 1, lq);
        }
        __syncthreads();
    }
    if (tid < 4) {
        const float s = sred[(2 * tid) * 2] + sred[(2 * tid + 1) * 2];
        const float q = sred[(2 * tid) * 2 + 1] + sred[(2 * tid + 1) * 2 + 1];
        const int hg = (n0 >> 6) + tid;
        g_part[(bb * 16 + hg) * 16 + mchunk] = make_float2(s, q);
    }
    TCGEN05_FENCE_BEFORE();
    __syncthreads();
    if (warp == 4) TCGEN05_DEALLOC(tmem, 256);
#else
    for (int idx = tid; idx < 128 * 256; idx += GT) {
        const int i = idx >> 8, j = idx & 255;
        float acc = 0.f;
        for (int k = 0; k < D_; k++) {
            const float a = __bfloat162float(*(const __nv_bfloat16*)((const char*)g_ahi + offA(m0 + i, k)))
                          + __bfloat162float(*(const __nv_bfloat16*)((const char*)g_alo + offA(m0 + i, k)));
            const float w = __bfloat162float(*(const __nv_bfloat16*)((const char*)Bhi + offW(n0 + j, k)))
                          + __bfloat162float(*(const __nv_bfloat16*)((const char*)Blo + offW(n0 + j, k)));
            acc = fmaf(a, w, acc);
        }
        const float v = acc + bo[n0 + j];
        const int m = m0 + i;
        C[(size_t)m * D_ + n0 + j] = v;
        float* gp = (float*)&g_part[(bb * 16 + ((n0 + j) >> 6)) * 16 + mchunk];
        atomicAdd(gp, v);
        atomicAdd(gp + 1, v * v);
    }
#endif
}

// ---------------- merged prep: W^T tiled split (z<4) + x tiled split (z==4) -
__global__ __launch_bounds__(256) void prep(
    const float* __restrict__ x,
    const float* __restrict__ W0, const float* __restrict__ W1,
    const float* __restrict__ W2, const float* __restrict__ W3)
{
    const int z = blockIdx.z;
    const int tx = threadIdx.x, ty = threadIdx.y;
    const int tid = ty * 32 + tx;
    if (z == 4) {
        if (blockIdx.x == 0 && blockIdx.y == 0) {
            for (int i = tid; i < 512; i += 256) g_part[i] = make_float2(0.f, 0.f);
        }
        const int u0 = (blockIdx.y * 32 + blockIdx.x) * 256 + tid;
#pragma unroll
        for (int r = 0; r < 4; r++) {
            const int i = (u0 + r * 262144) << 2;
            float4 v = *(const float4*)(x + i);
            const size_t o = offA(i >> 10, i & 1023);
            __nv_bfloat16 h0 = __float2bfloat16_rn(v.x);
            __nv_bfloat16 h1 = __float2bfloat16_rn(v.y);
            __nv_bfloat16 h2 = __float2bfloat16_rn(v.z);
            __nv_bfloat16 h3 = __float2bfloat16_rn(v.w);
            *(__nv_bfloat162*)((char*)g_xhi + o)     = __halves2bfloat162(h0, h1);
            *(__nv_bfloat162*)((char*)g_xhi + o + 4) = __halves2bfloat162(h2, h3);
            __nv_bfloat16 l0 = __float2bfloat16_rn(v.x - __bfloat162float(h0));
            __nv_bfloat16 l1 = __float2bfloat16_rn(v.y - __bfloat162float(h1));
            __nv_bfloat16 l2 = __float2bfloat16_rn(v.z - __bfloat162float(h2));
            __nv_bfloat16 l3 = __float2bfloat16_rn(v.w - __bfloat162float(h3));
            *(__nv_bfloat162*)((char*)g_xlo + o)     = __halves2bfloat162(l0, l1);
            *(__nv_bfloat162*)((char*)g_xlo + o + 4) = __halves2bfloat162(l2, l3);
        }
        return;
    }
    const float* W = (z == 0) ? W0 : (z == 1) ? W1 : (z == 2) ? W2 : W3;
    __nv_bfloat16* Hi = g_wthi[z];
    __nv_bfloat16* Lo = g_wtlo[z];
    __shared__ float t[32][33];
    const int n0 = blockIdx.x << 5, k0 = blockIdx.y << 5;
#pragma unroll
    for (int i = 0; i < 4; i++)
        t[ty + 8 * i][tx] = W[(size_t)(k0 + ty + 8 * i) * D_ + n0 + tx];
    __syncthreads();
#pragma unroll
    for (int i = 0; i < 4; i++) {
        const float v = t[tx][ty + 8 * i];
        __nv_bfloat16 h = __float2bfloat16_rn(v);
        __nv_bfloat16 l = __float2bfloat16_rn(v - __bfloat162float(h));
        const size_t o = offW(n0 + ty + 8 * i, k0 + tx);
        *(__nv_bfloat16*)((char*)Hi + o) = h;
        *(__nv_bfloat16*)((char*)Lo + o) = l;
    }
}

// ---------------- tcgen05 windowed decay attention ---------------------------
// CTA: 128 q rows x one (b,h). 256 threads, single KV stage, in-place S,
// TMEM 128 cols, 3 CTAs/SM. Epilogue writes g_a in GEMM-tiled layout.
#define ATT_IDESC 0x08100490u   // F32 acc, bf16, N=64, M=128
#define SO_BAR_S 0
#define SO_BAR_V 8
#define SO_TMEM  16
#define SO_TBL   1024
#define SO_QHI   3072
#define SO_QLO   (SO_QHI + 16384)
#define SO_KHI   (SO_QLO + 16384)        // 35840
#define SO_KLO   (SO_KHI + 8192)
#define SO_VHI   (SO_KLO + 8192)
#define SO_VLO   (SO_VHI + 8192)
#define ATT_SMEM (SO_VLO + 8192)         // 68608 bytes -> 3 CTAs/SM
// TMEM cols: O [0,64), S [64,128). Convert in-place: hi -> 64+, lo -> 96+.

__global__ __launch_bounds__(256, 3) void attn_tc()
{
    const int tid = threadIdx.x;
    const int bh = blockIdx.x;            // 0..31
    const int qp = 15 - blockIdx.y;       // heavy tiles first
    const int b = bh >> 4, h = bh & 15;
    const int qb = qp << 7;               // token base within batch
    const int qt0 = qp << 1;
    int jt0 = qt0 - WIN_TILES; if (jt0 < 0) jt0 = 0;
    const int nt = (qt0 + 1) - jt0 + 1;

#if defined(__CUDA_ARCH_FEAT_SM103_ALL)
    const unsigned sb = smem_u32(sm_raw);
    const int warp = tid >> 5, lane = tid & 31;
    const int sub = warp & 3;             // TMEM subpartition
    const int chalf = warp >> 2;          // column half (0/1)

    if (warp == 0) { TCGEN05_ALLOC(sb + SO_TMEM, 128); TCGEN05_RELINQ(); }
    if (tid == 0) {
        MBARRIER_INIT(sb + SO_BAR_S, 1);
        MBARRIER_INIT(sb + SO_BAR_V, 1);
    }
    float* tbl = (float*)(sm_raw + SO_TBL);
    for (int d = tid; d < 512; d += 256)
        tbl[d] = exp2f((float)d * LOG2DECAY);

    const char* kh0 = (const char*)(g_khi + ((size_t)(b * S_)) * D_ + h * HD_);
    const char* kl0 = (const char*)(g_klo + ((size_t)(b * S_)) * D_ + h * HD_);
    const char* vh0 = (const char*)(g_vthi + (size_t)bh * HD_ * S_);
    const char* vl0 = (const char*)(g_vtlo + (size_t)bh * HD_ * S_);

    // Q tiles: 128 rows x 128B, hi+lo
    {
        const char* qh = (const char*)(g_qhi + ((size_t)(b * S_ + qb)) * D_ + h * HD_);
        const char* ql = (const char*)(g_qlo + ((size_t)(b * S_ + qb)) * D_ + h * HD_);
        for (int g = tid; g < 1024; g += 256) {
            const int row = g >> 3, c = g & 7;
            const unsigned so = SWZ((unsigned)(row * 128 + c * 16));
            CP_ASYNC16(sb + SO_QHI + so, qh + (size_t)row * (D_ * 2) + c * 16);
            CP_ASYNC16(sb + SO_QLO + so, ql + (size_t)row * (D_ * 2) + c * 16);
        }
    }
    CP_COMMIT();
    __syncthreads();

    unsigned tmem;
    asm volatile("ld.shared.b32 %0, [%1];" : "=r"(tmem) : "r"(sb + SO_TMEM));

    const unsigned long long dQhi = sdesc(sb + SO_QHI), dQlo = sdesc(sb + SO_QLO);
    const unsigned long long dKhi = sdesc(sb + SO_KHI), dKlo = sdesc(sb + SO_KLO);
    const unsigned long long dVhi = sdesc(sb + SO_VHI), dVlo = sdesc(sb + SO_VLO);

    unsigned phs = 0, phv = 0;
    const int qrow = qb + sub * 32 + lane;                 // q token within batch

    for (int it = 0; it < nt; it++) {
        const int jt = jt0 + it;

        // V-MMA(it-1) must finish before KV smem / S cols are reused
        if (it > 0) { MBARRIER_WAIT_PARITY(sb + SO_BAR_V, phv); phv ^= 1; }

        // load KV(it)
        {
            const size_t koff = (size_t)(jt << 6);
            for (int g = tid; g < 512; g += 256) {
                const int row = g >> 3, c = g & 7;
                const unsigned so = SWZ((unsigned)(row * 128 + c * 16));
                CP_ASYNC16(sb + SO_KHI + so, kh0 + (koff + row) * (D_ * 2) + c * 16);
                CP_ASYNC16(sb + SO_KLO + so, kl0 + (koff + row) * (D_ * 2) + c * 16);
                CP_ASYNC16(sb + SO_VHI + so, vh0 + ((size_t)row * S_ + (jt << 6)) * 2 + c * 16);
                CP_ASYNC16(sb + SO_VLO + so, vl0 + ((size_t)row * S_ + (jt << 6)) * 2 + c * 16);
            }
            CP_COMMIT();
        }
        CP_WAIT0();
        FENCE_PROXY_ASYNC();
        __syncthreads();

        // S = Q K^T  (S at tmem+64, fp32)
        if (tid == 0) {
#pragma unroll
            for (int k = 0; k < 4; k++) {
                const unsigned long long off = 2ull * k;
                mma_f16_ss(tmem + 64, dQhi + off, dKhi + off, ATT_IDESC, k > 0 ? 1u : 0u);
                mma_f16_ss(tmem + 64, dQhi + off, dKlo + off, ATT_IDESC, 1u);
                mma_f16_ss(tmem + 64, dQlo + off, dKhi + off, ATT_IDESC, 1u);
            }
            TCGEN05_COMMIT(sb + SO_BAR_S);
        }
        MBARRIER_WAIT_PARITY(sb + SO_BAR_S, phs); phs ^= 1;
        TCGEN05_FENCE_AFTER();

        // convert: read S fp32, mask, split -> write back IN PLACE as bf16x2
        const int kbase = jt << 6;
        {
            unsigned r[32];
            TCGEN05_LD_32X32B_X32(r, tmem + 64 + chalf * 32);
            TCGEN05_WAIT_LD();
            __syncthreads();             // ALL reads complete before any write
#pragma unroll
            for (int half = 0; half < 2; half++) {
                unsigned hi8[8], lo8[8];
#pragma unroll
                for (int c = 0; c < 16; c += 2) {
                    const int col = chalf * 32 + half * 16 + c;
                    const int d0 = qrow - (kbase + col);
                    const int d1 = d0 - 1;
                    const float f0 = (d0 >= 0) ? tbl[d0] : 0.f;
                    const float f1 = (d1 >= 0) ? tbl[d1] : 0.f;
                    const float v0 = __uint_as_float(r[half * 16 + c]) * f0;
                    const float v1 = __uint_as_float(r[half * 16 + c + 1]) * f1;
                    __nv_bfloat16 h0 = __float2bfloat16_rn(v0);
                    __nv_bfloat16 h1 = __float2bfloat16_rn(v1);
                    __nv_bfloat16 l0 = __float2bfloat16_rn(v0 - __bfloat162float(h0));
                    __nv_bfloat16 l1 = __float2bfloat16_rn(v1 - __bfloat162float(h1));
                    __nv_bfloat162 ph = __halves2bfloat162(h0, h1);
                    __nv_bfloat162 pl = __halves2bfloat162(l0, l1);
                    hi8[c >> 1] = *reinterpret_cast<unsigned*>(&ph);
                    lo8[c >> 1] = *reinterpret_cast<unsigned*>(&pl);
                }
                const unsigned cbase = (unsigned)(chalf * 16 + half * 8);
                TCGEN05_ST_32X32B_X8(tmem + 64 + cbase, hi8);
                TCGEN05_ST_32X32B_X8(tmem + 96 + cbase, lo8);
            }
            TCGEN05_WAIT_ST();
        }
        TCGEN05_FENCE_BEFORE();
        __syncthreads();

        // O += S V  (TS: A = S bf16 in TMEM, B = V^T in smem)
        if (tid == 0) {
            TCGEN05_FENCE_AFTER();
#pragma unroll
            for (int k = 0; k < 4; k++) {
                const unsigned long long off = 2ull * k;
                mma_f16_ts(tmem, tmem + 64 + k * 8, dVhi + off, ATT_IDESC,
                           (it == 0 && k == 0) ? 0u : 1u);
                mma_f16_ts(tmem, tmem + 64 + k * 8, dVlo + off, ATT_IDESC, 1u);
                mma_f16_ts(tmem, tmem + 96 + k * 8, dVhi + off, ATT_IDESC, 1u);
            }
            TCGEN05_COMMIT(sb + SO_BAR_V);
        }
    }
    MBARRIER_WAIT_PARITY(sb + SO_BAR_V, phv);
    TCGEN05_FENCE_AFTER();

    // epilogue: O -> smem (stride-65) -> g_a in GEMM-tiled swizzled layout
    {
        float* stg = (float*)(sm_raw + SO_QHI);   // 33 KB in dead Q/K region
        unsigned r[32];
        TCGEN05_LD_32X32B_X32(r, tmem + chalf * 32);
        TCGEN05_WAIT_LD();
        float* srow = stg + (sub * 32 + lane) * 65 + chalf * 32;
#pragma unroll
        for (int j = 0; j < 32; j++) srow[j] = __uint_as_float(r[j]);
        TCGEN05_FENCE_BEFORE();
        __syncthreads();
        const size_t abase = ((size_t)((((b * S_) + qb) >> 7) * 16 + h)) << 14;
        for (int g = tid; g < 4096; g += 256) {
            const int row = g >> 5, cp = (g & 31) << 1;
            const size_t o = abase + SWZ((unsigned)(row * 128 + ((cp >> 3) << 4))) + ((cp & 7) << 1);
            const float v0 = stg[row * 65 + cp], v1 = stg[row * 65 + cp + 1];
            __nv_bfloat16 h0 = __float2bfloat16_rn(v0);
            __nv_bfloat16 h1 = __float2bfloat16_rn(v1);
            __nv_bfloat16 l0 = __float2bfloat16_rn(v0 - __bfloat162float(h0));
            __nv_bfloat16 l1 = __float2bfloat16_rn(v1 - __bfloat162float(h1));
            *(__nv_bfloat162*)((char*)g_ahi + o) = __halves2bfloat162(h0, h1);
            *(__nv_bfloat162*)((char*)g_alo + o) = __halves2bfloat162(l0, l1);
        }
    }
    __syncthreads();
    if (warp == 0) TCGEN05_DEALLOC(tmem, 128);
#else
    // -------- correct (very slow) fallback: never runs on GB300 -------------
    const int jlo = jt0 << 6;
    for (int e = tid; e < 128 * HD_; e += 256) {
        const int i = e >> 6, d = e & 63;
        const int qr = qb + i;
        float acc = 0.f;
        for (int j = jlo; j <= qr; j++) {
            float s = 0.f;
            const size_t qo = (size_t)(b * S_ + qr) * D_ + h * HD_;
            const size_t ko = (size_t)(b * S_ + j) * D_ + h * HD_;
            for (int k = 0; k < HD_; k++) {
                const float qv = __bfloat162float(g_qhi[qo + k]) + __bfloat162float(g_qlo[qo + k]);
                const float kv = __bfloat162float(g_khi[ko + k]) + __bfloat162float(g_klo[ko + k]);
                s = fmaf(qv, kv, s);
            }
            const float f = exp2f((float)(qr - j) * LOG2DECAY);
            const size_t vo = (size_t)(bh * HD_ + d) * S_ + j;
            const float vv = __bfloat162float(g_vthi[vo]) + __bfloat162float(g_vtlo[vo]);
            acc = fmaf(s * f, vv, acc);
        }
        const size_t o = offA(b * S_ + qr, h * HD_ + d);
        __nv_bfloat16 hh = __float2bfloat16_rn(acc);
        *(__nv_bfloat16*)((char*)g_ahi + o) = hh;
        *(__nv_bfloat16*)((char*)g_alo + o) =
            __float2bfloat16_rn(acc - __bfloat162float(hh));
    }
#endif
}

// ---------------- GroupNorm (partials fused into proj epilogue) -------------
__global__ void gn_stats()
{
    const int g = threadIdx.x;
    float s = 0.f, q = 0.f;
    for (int c = 0; c < 16; c++) {
        float2 p = g_part[g * 16 + c];
        s += p.x; q += p.y;
    }
    const float n = (float)(S_ * HD_);
    const float mu = s / n;
    const float var = q / n - mu * mu;
    g_stats[g] = make_float2(mu, rsqrtf(var + 1e-5f));
}

__global__ __launch_bounds__(256) void gn_apply(
    const float* __restrict__ gamma, const float* __restrict__ beta,
    float* __restrict__ out)
{
    const int t = blockIdx.x * 256 + threadIdx.x;
    const int base = t << 2;
    const int d = base & (D_ - 1);
    const int row = base >> 10;
    const int b = row >> 11;
    const float2 st = g_stats[(b << 4) | (d >> 6)];
    const float4 v  = *(const float4*)(g_proj + base);
    const float4 gm = *(const float4*)(gamma + d);
    const float4 bt = *(const float4*)(beta + d);
    float4 o;
    o.x = (v.x - st.x) * st.y * gm.x + bt.x;
    o.y = (v.y - st.x) * st.y * gm.y + bt.y;
    o.z = (v.z - st.x) * st.y * gm.z + bt.z;
    o.w = (v.w - st.x) * st.y * gm.w + bt.w;
    *(float4*)(out + base) = o;
}

// ---------------- launch ----------------------------------------------------
extern "C" void kernel_launch(void* const* d_in, const int* in_sizes, int n_in,
                              void* d_out, int out_size)
{
    (void)in_sizes; (void)n_in; (void)out_size;
    const float* x     = (const float*)d_in[0];
    const float* Wq    = (const float*)d_in[1];
    const float* bq    = (const float*)d_in[2];
    const float* Wk    = (const float*)d_in[3];
    const float* bk    = (const float*)d_in[4];
    const float* Wv    = (const float*)d_in[5];
    const float* bv    = (const float*)d_in[6];
    const float* Wo    = (const float*)d_in[7];
    const float* bo    = (const float*)d_in[8];
    const float* gamma = (const float*)d_in[9];
    const float* beta  = (const float*)d_in[10];
    float* out = (float*)d_out;

    cudaFuncSetAttribute(gemm_tc128,
                         cudaFuncAttributeMaxDynamicSharedMemorySize, DSM128);
    cudaFuncSetAttribute(gemm_tc256,
                         cudaFuncAttributeMaxDynamicSharedMemorySize, DSM256);
    cudaFuncSetAttribute(attn_tc,
                         cudaFuncAttributeMaxDynamicSharedMemorySize, ATT_SMEM);

    prep<<<dim3(32, 32, 5), dim3(32, 8)>>>(x, Wq, Wk, Wv, Wo);
    gemm_tc128<<<dim3(8, 32, 3), GT, DSM128>>>(bq, bk, bv);
    attn_tc<<<dim3(32, 16), 256, ATT_SMEM>>>();
    gemm_tc256<<<dim3(4, 32, 1), GT, DSM256>>>(bo);
    gn_stats<<<1, 32>>>();
    gn_apply<<<(M_ * D_) / (256 * 4), 256>>>(gamma, beta, out);
}